// round 1
// baseline (speedup 1.0000x reference)
#include <cuda_runtime.h>

#define D 128
constexpr int MAXN = 50048;
constexpr int MAXE = 1000192;

// ---------------- scratch (static device globals; no allocation) ----------------
__device__ float g_deg  [3 * MAXN];
__device__ float g_dinv [3 * MAXN];
__device__ int   g_count[MAXN];
__device__ int   g_rowstart[MAXN + 1];
__device__ int   g_cursor[MAXN];
__device__ int   g_srcp [MAXE];
__device__ float g_effp [3 * MAXE];
__device__ float g_agg  [3 * MAXN * D];   // [c][N][D]
__device__ float g_h    [MAXN * D];       // inter-layer activations
__device__ int   g_blksum[256];
__device__ int   g_blkoff[256];

// ---------------- init: deg = 1, count = 0 ----------------
__global__ void k_init(int N) {
    int i = blockIdx.x * blockDim.x + threadIdx.x;
    if (i < 3 * N) g_deg[i] = 1.0f;
    if (i < N)     g_count[i] = 0;
}

// ---------------- edge pass 1: degree accumulation + target histogram ----------------
__global__ void k_edge1(const int* __restrict__ ei,
                        const float* __restrict__ asp, const float* __restrict__ actx,
                        const float* __restrict__ alat,
                        const float* __restrict__ wsp, const float* __restrict__ wctx,
                        const float* __restrict__ wlat, int N, int E) {
    int e = blockIdx.x * blockDim.x + threadIdx.x;
    if (e >= E) return;
    int t = ei[E + e];
    float e0 = asp[e] * wsp[e];
    float e1 = actx[e] * wctx[e];
    float e2 = alat[e] * wlat[e];
    atomicAdd(&g_deg[t],         e0);
    atomicAdd(&g_deg[N + t],     e1);
    atomicAdd(&g_deg[2 * N + t], e2);
    atomicAdd(&g_count[t], 1);
}

// ---------------- block scans (Hillis-Steele, 256 wide) ----------------
__device__ __forceinline__ int block_incl_scan(int v, int* s) {
    int tid = threadIdx.x;
    s[tid] = v;
    __syncthreads();
    #pragma unroll
    for (int o = 1; o < 256; o <<= 1) {
        int t = (tid >= o) ? s[tid - o] : 0;
        __syncthreads();
        s[tid] += t;
        __syncthreads();
    }
    return s[tid];
}

__global__ void k_scan1(int N) {
    __shared__ int s[256];
    int i = blockIdx.x * 256 + threadIdx.x;
    int v = (i < N) ? g_count[i] : 0;
    block_incl_scan(v, s);
    if (threadIdx.x == 255) g_blksum[blockIdx.x] = s[255];
}

__global__ void k_scan2(int nblk, int E, int N) {
    __shared__ int s[256];
    int tid = threadIdx.x;
    int v = (tid < nblk) ? g_blksum[tid] : 0;
    int inc = block_incl_scan(v, s);
    g_blkoff[tid] = inc - v;              // exclusive
    if (tid == 0) g_rowstart[N] = E;
}

__global__ void k_scan3(int N) {
    __shared__ int s[256];
    int i = blockIdx.x * 256 + threadIdx.x;
    int v = (i < N) ? g_count[i] : 0;
    int inc = block_incl_scan(v, s);
    if (i < N) {
        int excl = inc - v + g_blkoff[blockIdx.x];
        g_rowstart[i] = excl;
        g_cursor[i] = excl;
    }
}

// ---------------- edge pass 2: scatter edges into CSR slots ----------------
__global__ void k_edge2(const int* __restrict__ ei,
                        const float* __restrict__ asp, const float* __restrict__ actx,
                        const float* __restrict__ alat,
                        const float* __restrict__ wsp, const float* __restrict__ wctx,
                        const float* __restrict__ wlat, int N, int E) {
    int e = blockIdx.x * blockDim.x + threadIdx.x;
    if (e >= E) return;
    int t = ei[E + e];
    int s = ei[e];
    int p = atomicAdd(&g_cursor[t], 1);
    g_srcp[p] = s;
    g_effp[p]         = asp[e]  * wsp[e];
    g_effp[E + p]     = actx[e] * wctx[e];
    g_effp[2 * E + p] = alat[e] * wlat[e];
}

// ---------------- per-layer: dinv = clip(deg,1e-6)^p ----------------
__global__ void k_dinv(const float* __restrict__ deg_power, int l, int N) {
    int i = blockIdx.x * blockDim.x + threadIdx.x;
    if (i >= 3 * N) return;
    int c = i / N;
    float p = deg_power[l * 3 + c];
    float d = fmaxf(g_deg[i], 1e-6f);
    g_dinv[i] = powf(d, p);
}

// ---------------- aggregate: one block per target node, 3 channels in regs ----------------
__global__ void k_agg(const float* __restrict__ x, int use_h, int N, int E) {
    int t = blockIdx.x;
    if (t >= N) return;
    const float* __restrict__ X = use_h ? g_h : x;
    int tid = threadIdx.x;   // 128
    int s = g_rowstart[t];
    int eend = g_rowstart[t + 1];
    float dt0 = g_dinv[t], dt1 = g_dinv[N + t], dt2 = g_dinv[2 * N + t];
    float a0 = 0.f, a1 = 0.f, a2 = 0.f;
    for (int p = s; p < eend; p++) {
        int sid = __ldg(&g_srcp[p]);
        float n0 = __ldg(&g_effp[p])         * dt0 * __ldg(&g_dinv[sid]);
        float n1 = __ldg(&g_effp[E + p])     * dt1 * __ldg(&g_dinv[N + sid]);
        float n2 = __ldg(&g_effp[2 * E + p]) * dt2 * __ldg(&g_dinv[2 * N + sid]);
        float xv = __ldg(&X[sid * D + tid]);
        a0 = fmaf(n0, xv, a0);
        a1 = fmaf(n1, xv, a1);
        a2 = fmaf(n2, xv, a2);
    }
    g_agg[t * D + tid]               = a0;
    g_agg[N * D + t * D + tid]       = a1;
    g_agg[2 * N * D + t * D + tid]   = a2;
}

// ---------------- fused GEMM: out = [X|agg0|agg1|agg2] @ [Wself;W3_0;W3_1;W3_2] + bias
//                  (+ LayerNorm + ReLU for non-last layer) ----------------
template <bool LAST>
__global__ void __launch_bounds__(256, 4)
k_gemm(const float* __restrict__ x, int use_h,
       const float* __restrict__ Wself, const float* __restrict__ W3,
       const float* __restrict__ bias,
       const float* __restrict__ lng, const float* __restrict__ lnb,
       float* __restrict__ dout, int N) {
    constexpr int BM = 64, BK = 16;
    __shared__ float As[BK][BM + 4];
    __shared__ float Bs[BK][D];

    const float* __restrict__ X = use_h ? g_h : x;
    float* __restrict__ out = LAST ? dout : g_h;

    int bm0 = blockIdx.x * BM;
    int tid = threadIdx.x;
    int tx = tid & 15;        // col group
    int ty = tid >> 4;        // row group

    float acc[4][8];
    #pragma unroll
    for (int m = 0; m < 4; m++)
        #pragma unroll
        for (int n = 0; n < 8; n++) acc[m][n] = 0.f;

    const float* Ap[4] = { X, g_agg, g_agg + N * D, g_agg + 2 * N * D };
    const float* Bp[4] = { Wself, W3, W3 + D * D, W3 + 2 * D * D };

    for (int c = 0; c < 4; c++) {
        const float* __restrict__ A = Ap[c];
        const float* __restrict__ B = Bp[c];
        for (int kk = 0; kk < D; kk += BK) {
            // load A tile (64 x 16), transposed into As[k][row]
            #pragma unroll
            for (int i = 0; i < 4; i++) {
                int l = tid + i * 256;
                int k = l & 15, r = l >> 4;
                int gr = bm0 + r;
                As[k][r] = (gr < N) ? A[gr * D + kk + k] : 0.f;
            }
            // load B tile (16 x 128)
            #pragma unroll
            for (int i = 0; i < 8; i++) {
                int l = tid + i * 256;
                int j = l & 127, k = l >> 7;
                Bs[k][j] = B[(kk + k) * D + j];
            }
            __syncthreads();
            #pragma unroll
            for (int k = 0; k < BK; k++) {
                float4 av = *(const float4*)&As[k][ty * 4];
                float4 b0 = *(const float4*)&Bs[k][tx * 8];
                float4 b1 = *(const float4*)&Bs[k][tx * 8 + 4];
                float a[4] = { av.x, av.y, av.z, av.w };
                float b[8] = { b0.x, b0.y, b0.z, b0.w, b1.x, b1.y, b1.z, b1.w };
                #pragma unroll
                for (int m = 0; m < 4; m++)
                    #pragma unroll
                    for (int n = 0; n < 8; n++)
                        acc[m][n] = fmaf(a[m], b[n], acc[m][n]);
            }
            __syncthreads();
        }
    }

    // epilogue
    float bv[8], gv[8], bb[8];
    #pragma unroll
    for (int n = 0; n < 8; n++) {
        int j = tx * 8 + n;
        bv[n] = bias[j];
        if (!LAST) { gv[n] = lng[j]; bb[n] = lnb[j]; }
    }
    #pragma unroll
    for (int m = 0; m < 4; m++) {
        int gr = bm0 + ty * 4 + m;
        float v[8];
        #pragma unroll
        for (int n = 0; n < 8; n++) v[n] = acc[m][n] + bv[n];
        if (!LAST) {
            // row is fully held by the 16 lanes sharing ty (xor over tx bits)
            float s = 0.f, sq = 0.f;
            #pragma unroll
            for (int n = 0; n < 8; n++) { s += v[n]; sq += v[n] * v[n]; }
            #pragma unroll
            for (int o = 1; o < 16; o <<= 1) {
                s  += __shfl_xor_sync(0xffffffffu, s, o);
                sq += __shfl_xor_sync(0xffffffffu, sq, o);
            }
            float mu = s * (1.0f / 128.0f);
            float var = sq * (1.0f / 128.0f) - mu * mu;
            float rs = rsqrtf(var + 1e-5f);
            #pragma unroll
            for (int n = 0; n < 8; n++) {
                float y = (v[n] - mu) * rs * gv[n] + bb[n];
                v[n] = fmaxf(y, 0.f);
            }
        }
        if (gr < N) {
            float4 o0 = make_float4(v[0], v[1], v[2], v[3]);
            float4 o1 = make_float4(v[4], v[5], v[6], v[7]);
            *(float4*)&out[gr * D + tx * 8]     = o0;
            *(float4*)&out[gr * D + tx * 8 + 4] = o1;
        }
    }
}

// ---------------- launch ----------------
extern "C" void kernel_launch(void* const* d_in, const int* in_sizes, int n_in,
                              void* d_out, int out_size) {
    const float* x    = (const float*)d_in[0];
    const int*   ei   = (const int*)d_in[1];
    const float* asp  = (const float*)d_in[2];
    const float* actx = (const float*)d_in[3];
    const float* alat = (const float*)d_in[4];
    const float* wsp  = (const float*)d_in[5];
    const float* wctx = (const float*)d_in[6];
    const float* wlat = (const float*)d_in[7];
    const float* W3   = (const float*)d_in[8];   // [L,3,D,D]
    const float* Wslf = (const float*)d_in[9];   // [L,D,D]
    const float* bias = (const float*)d_in[10];  // [L,D]
    const float* degp = (const float*)d_in[11];  // [L,3]
    const float* lng  = (const float*)d_in[12];
    const float* lnb  = (const float*)d_in[13];
    float* out = (float*)d_out;

    int N = in_sizes[0] / D;
    int E = in_sizes[2];
    int L = in_sizes[10] / D;
    int nblk = (N + 255) / 256;

    k_init<<<(3 * N + 255) / 256, 256>>>(N);
    k_edge1<<<(E + 255) / 256, 256>>>(ei, asp, actx, alat, wsp, wctx, wlat, N, E);
    k_scan1<<<nblk, 256>>>(N);
    k_scan2<<<1, 256>>>(nblk, E, N);
    k_scan3<<<nblk, 256>>>(N);
    k_edge2<<<(E + 255) / 256, 256>>>(ei, asp, actx, alat, wsp, wctx, wlat, N, E);

    int gemm_grid = (N + 63) / 64;
    for (int l = 0; l < L; l++) {
        int use_h = (l > 0) ? 1 : 0;
        k_dinv<<<(3 * N + 255) / 256, 256>>>(degp, l, N);
        k_agg<<<N, 128>>>(x, use_h, N, E);
        const float* W3l = W3 + l * 3 * D * D;
        const float* Wsl = Wslf + l * D * D;
        const float* bl  = bias + l * D;
        if (l == L - 1)
            k_gemm<true><<<gemm_grid, 256>>>(x, use_h, Wsl, W3l, bl, lng, lnb, out, N);
        else
            k_gemm<false><<<gemm_grid, 256>>>(x, use_h, Wsl, W3l, bl, lng, lnb, out, N);
    }
}

// round 2
// speedup vs baseline: 1.0229x; 1.0229x over previous
#include <cuda_runtime.h>

#define D 128
constexpr int MAXN = 50048;
constexpr int MAXE = 1000192;

// ---------------- scratch (static device globals; no allocation) ----------------
__device__ float g_deg  [3 * MAXN];
__device__ float g_dinv [3 * MAXN];
__device__ int   g_count[MAXN];
__device__ int   g_rowstart[MAXN + 1];
__device__ int   g_cursor[MAXN];
__device__ int   g_srcp [MAXE];
__device__ float g_effp [3 * MAXE];
__device__ float g_agg  [3 * MAXN * D];   // [c][N][D]
__device__ float g_h    [MAXN * D];       // inter-layer activations
__device__ int   g_blksum[256];
__device__ int   g_blkoff[256];

// ---------------- init: deg = 1, count = 0 ----------------
__global__ void k_init(int N) {
    int i = blockIdx.x * blockDim.x + threadIdx.x;
    if (i < 3 * N) g_deg[i] = 1.0f;
    if (i < N)     g_count[i] = 0;
}

// ---------------- edge pass 1: degree accumulation + target histogram ----------------
__global__ void k_edge1(const int* __restrict__ ei,
                        const float* __restrict__ asp, const float* __restrict__ actx,
                        const float* __restrict__ alat,
                        const float* __restrict__ wsp, const float* __restrict__ wctx,
                        const float* __restrict__ wlat, int N, int E) {
    int e = blockIdx.x * blockDim.x + threadIdx.x;
    if (e >= E) return;
    int t = ei[E + e];
    float e0 = asp[e] * wsp[e];
    float e1 = actx[e] * wctx[e];
    float e2 = alat[e] * wlat[e];
    atomicAdd(&g_deg[t],         e0);
    atomicAdd(&g_deg[N + t],     e1);
    atomicAdd(&g_deg[2 * N + t], e2);
    atomicAdd(&g_count[t], 1);
}

// ---------------- block scans (Hillis-Steele, 256 wide) ----------------
__device__ __forceinline__ int block_incl_scan(int v, int* s) {
    int tid = threadIdx.x;
    s[tid] = v;
    __syncthreads();
    #pragma unroll
    for (int o = 1; o < 256; o <<= 1) {
        int t = (tid >= o) ? s[tid - o] : 0;
        __syncthreads();
        s[tid] += t;
        __syncthreads();
    }
    return s[tid];
}

__global__ void k_scan1(int N) {
    __shared__ int s[256];
    int i = blockIdx.x * 256 + threadIdx.x;
    int v = (i < N) ? g_count[i] : 0;
    block_incl_scan(v, s);
    if (threadIdx.x == 255) g_blksum[blockIdx.x] = s[255];
}

__global__ void k_scan2(int nblk, int E, int N) {
    __shared__ int s[256];
    int tid = threadIdx.x;
    int v = (tid < nblk) ? g_blksum[tid] : 0;
    int inc = block_incl_scan(v, s);
    g_blkoff[tid] = inc - v;              // exclusive
    if (tid == 0) g_rowstart[N] = E;
}

__global__ void k_scan3(int N) {
    __shared__ int s[256];
    int i = blockIdx.x * 256 + threadIdx.x;
    int v = (i < N) ? g_count[i] : 0;
    int inc = block_incl_scan(v, s);
    if (i < N) {
        int excl = inc - v + g_blkoff[blockIdx.x];
        g_rowstart[i] = excl;
        g_cursor[i] = excl;
    }
}

// ---------------- edge pass 2: scatter edges into CSR slots ----------------
__global__ void k_edge2(const int* __restrict__ ei,
                        const float* __restrict__ asp, const float* __restrict__ actx,
                        const float* __restrict__ alat,
                        const float* __restrict__ wsp, const float* __restrict__ wctx,
                        const float* __restrict__ wlat, int N, int E) {
    int e = blockIdx.x * blockDim.x + threadIdx.x;
    if (e >= E) return;
    int t = ei[E + e];
    int s = ei[e];
    int p = atomicAdd(&g_cursor[t], 1);
    g_srcp[p] = s;
    g_effp[p]         = asp[e]  * wsp[e];
    g_effp[E + p]     = actx[e] * wctx[e];
    g_effp[2 * E + p] = alat[e] * wlat[e];
}

// ---------------- per-layer: dinv = clip(deg,1e-6)^p ----------------
__global__ void k_dinv(const float* __restrict__ deg_power, int l, int N) {
    int i = blockIdx.x * blockDim.x + threadIdx.x;
    if (i >= 3 * N) return;
    int c = i / N;
    float p = deg_power[l * 3 + c];
    float d = fmaxf(g_deg[i], 1e-6f);
    g_dinv[i] = powf(d, p);
}

// ---------------- aggregate: one block per target node, 3 channels in regs ----------------
__global__ void k_agg(const float* __restrict__ x, int use_h, int N, int E) {
    int t = blockIdx.x;
    if (t >= N) return;
    const float* __restrict__ X = use_h ? g_h : x;
    int tid = threadIdx.x;   // 128
    int s = g_rowstart[t];
    int eend = g_rowstart[t + 1];
    float dt0 = g_dinv[t], dt1 = g_dinv[N + t], dt2 = g_dinv[2 * N + t];
    float a0 = 0.f, a1 = 0.f, a2 = 0.f;
    for (int p = s; p < eend; p++) {
        int sid = __ldg(&g_srcp[p]);
        float n0 = __ldg(&g_effp[p])         * dt0 * __ldg(&g_dinv[sid]);
        float n1 = __ldg(&g_effp[E + p])     * dt1 * __ldg(&g_dinv[N + sid]);
        float n2 = __ldg(&g_effp[2 * E + p]) * dt2 * __ldg(&g_dinv[2 * N + sid]);
        float xv = __ldg(&X[sid * D + tid]);
        a0 = fmaf(n0, xv, a0);
        a1 = fmaf(n1, xv, a1);
        a2 = fmaf(n2, xv, a2);
    }
    g_agg[t * D + tid]               = a0;
    g_agg[N * D + t * D + tid]       = a1;
    g_agg[2 * N * D + t * D + tid]   = a2;
}

// ---------------- fused GEMM: out = [X|agg0|agg1|agg2] @ [Wself;W3_0;W3_1;W3_2] + bias
//                  (+ LayerNorm + ReLU for non-last layer) ----------------
template <bool LAST>
__global__ void __launch_bounds__(256, 4)
k_gemm(const float* __restrict__ x, int use_h,
       const float* __restrict__ Wself, const float* __restrict__ W3,
       const float* __restrict__ bias,
       const float* __restrict__ lng, const float* __restrict__ lnb,
       float* __restrict__ dout, int N) {
    constexpr int BM = 64, BK = 16;
    __shared__ float As[BK][BM + 4];
    __shared__ float Bs[BK][D];

    const float* __restrict__ X = use_h ? g_h : x;
    float* __restrict__ out = LAST ? dout : g_h;

    int bm0 = blockIdx.x * BM;
    int tid = threadIdx.x;
    int tx = tid & 15;        // col group
    int ty = tid >> 4;        // row group

    float acc[4][8];
    #pragma unroll
    for (int m = 0; m < 4; m++)
        #pragma unroll
        for (int n = 0; n < 8; n++) acc[m][n] = 0.f;

    const float* Ap[4] = { X, g_agg, g_agg + N * D, g_agg + 2 * N * D };
    const float* Bp[4] = { Wself, W3, W3 + D * D, W3 + 2 * D * D };

    for (int c = 0; c < 4; c++) {
        const float* __restrict__ A = Ap[c];
        const float* __restrict__ B = Bp[c];
        for (int kk = 0; kk < D; kk += BK) {
            // load A tile (64 x 16), transposed into As[k][row]
            #pragma unroll
            for (int i = 0; i < 4; i++) {
                int l = tid + i * 256;
                int k = l & 15, r = l >> 4;
                int gr = bm0 + r;
                As[k][r] = (gr < N) ? A[gr * D + kk + k] : 0.f;
            }
            // load B tile (16 x 128)
            #pragma unroll
            for (int i = 0; i < 8; i++) {
                int l = tid + i * 256;
                int j = l & 127, k = l >> 7;
                Bs[k][j] = B[(kk + k) * D + j];
            }
            __syncthreads();
            #pragma unroll
            for (int k = 0; k < BK; k++) {
                float4 av = *(const float4*)&As[k][ty * 4];
                float4 b0 = *(const float4*)&Bs[k][tx * 8];
                float4 b1 = *(const float4*)&Bs[k][tx * 8 + 4];
                float a[4] = { av.x, av.y, av.z, av.w };
                float b[8] = { b0.x, b0.y, b0.z, b0.w, b1.x, b1.y, b1.z, b1.w };
                #pragma unroll
                for (int m = 0; m < 4; m++)
                    #pragma unroll
                    for (int n = 0; n < 8; n++)
                        acc[m][n] = fmaf(a[m], b[n], acc[m][n]);
            }
            __syncthreads();
        }
    }

    // epilogue
    float bv[8], gv[8], bb[8];
    #pragma unroll
    for (int n = 0; n < 8; n++) {
        int j = tx * 8 + n;
        bv[n] = bias[j];
        if (!LAST) { gv[n] = lng[j]; bb[n] = lnb[j]; }
    }
    #pragma unroll
    for (int m = 0; m < 4; m++) {
        int gr = bm0 + ty * 4 + m;
        float v[8];
        #pragma unroll
        for (int n = 0; n < 8; n++) v[n] = acc[m][n] + bv[n];
        if (!LAST) {
            // row is fully held by the 16 lanes sharing ty (xor over tx bits)
            float s = 0.f, sq = 0.f;
            #pragma unroll
            for (int n = 0; n < 8; n++) { s += v[n]; sq += v[n] * v[n]; }
            #pragma unroll
            for (int o = 1; o < 16; o <<= 1) {
                s  += __shfl_xor_sync(0xffffffffu, s, o);
                sq += __shfl_xor_sync(0xffffffffu, sq, o);
            }
            float mu = s * (1.0f / 128.0f);
            float var = sq * (1.0f / 128.0f) - mu * mu;
            float rs = rsqrtf(var + 1e-5f);
            #pragma unroll
            for (int n = 0; n < 8; n++) {
                float y = (v[n] - mu) * rs * gv[n] + bb[n];
                v[n] = fmaxf(y, 0.f);
            }
        }
        if (gr < N) {
            float4 o0 = make_float4(v[0], v[1], v[2], v[3]);
            float4 o1 = make_float4(v[4], v[5], v[6], v[7]);
            *(float4*)&out[gr * D + tx * 8]     = o0;
            *(float4*)&out[gr * D + tx * 8 + 4] = o1;
        }
    }
}

// ---------------- launch ----------------
extern "C" void kernel_launch(void* const* d_in, const int* in_sizes, int n_in,
                              void* d_out, int out_size) {
    const float* x    = (const float*)d_in[0];
    const int*   ei   = (const int*)d_in[1];
    const float* asp  = (const float*)d_in[2];
    const float* actx = (const float*)d_in[3];
    const float* alat = (const float*)d_in[4];
    const float* wsp  = (const float*)d_in[5];
    const float* wctx = (const float*)d_in[6];
    const float* wlat = (const float*)d_in[7];
    const float* W3   = (const float*)d_in[8];   // [L,3,D,D]
    const float* Wslf = (const float*)d_in[9];   // [L,D,D]
    const float* bias = (const float*)d_in[10];  // [L,D]
    const float* degp = (const float*)d_in[11];  // [L,3]
    const float* lng  = (const float*)d_in[12];
    const float* lnb  = (const float*)d_in[13];
    float* out = (float*)d_out;

    int N = in_sizes[0] / D;
    int E = in_sizes[2];
    int L = in_sizes[10] / D;
    int nblk = (N + 255) / 256;

    k_init<<<(3 * N + 255) / 256, 256>>>(N);
    k_edge1<<<(E + 255) / 256, 256>>>(ei, asp, actx, alat, wsp, wctx, wlat, N, E);
    k_scan1<<<nblk, 256>>>(N);
    k_scan2<<<1, 256>>>(nblk, E, N);
    k_scan3<<<nblk, 256>>>(N);
    k_edge2<<<(E + 255) / 256, 256>>>(ei, asp, actx, alat, wsp, wctx, wlat, N, E);

    int gemm_grid = (N + 63) / 64;
    for (int l = 0; l < L; l++) {
        int use_h = (l > 0) ? 1 : 0;
        k_dinv<<<(3 * N + 255) / 256, 256>>>(degp, l, N);
        k_agg<<<N, 128>>>(x, use_h, N, E);
        const float* W3l = W3 + l * 3 * D * D;
        const float* Wsl = Wslf + l * D * D;
        const float* bl  = bias + l * D;
        if (l == L - 1)
            k_gemm<true><<<gemm_grid, 256>>>(x, use_h, Wsl, W3l, bl, lng, lnb, out, N);
        else
            k_gemm<false><<<gemm_grid, 256>>>(x, use_h, Wsl, W3l, bl, lng, lnb, out, N);
    }
}

// round 4
// speedup vs baseline: 2.0067x; 1.9618x over previous
#include <cuda_runtime.h>
#include <cuda_bf16.h>
#include <cstdint>

#define D 128
constexpr int MAXN = 50048;
constexpr int MAXE = 1000192;

// ---------------- scratch (static device globals; no allocation) ----------------
__device__ float g_deg  [3 * MAXN];
__device__ float g_dinv [3 * MAXN];
__device__ int   g_count[MAXN];
__device__ int   g_rowstart[MAXN + 1];
__device__ int   g_cursor[MAXN];
__device__ int   g_srcp [MAXE];
__device__ float g_effp [3 * MAXE];
__device__ float g_agg  [3 * MAXN * D];   // [c][N][D]
__device__ float g_h    [MAXN * D];       // inter-layer activations
__device__ int   g_blksum[256];
__device__ int   g_blkoff[256];
// split-bf16 weights, transposed to [l][c][n][k] (B as N x K, K-major)
__device__ __nv_bfloat16 g_Bhi[2 * 4 * D * D];
__device__ __nv_bfloat16 g_Blo[2 * 4 * D * D];

// ---------------- init: deg = 1, count = 0 ----------------
__global__ void k_init(int N) {
    int i = blockIdx.x * blockDim.x + threadIdx.x;
    if (i < 3 * N) g_deg[i] = 1.0f;
    if (i < N)     g_count[i] = 0;
}

// ---------------- edge pass 1: degree accumulation + target histogram ----------------
__global__ void k_edge1(const int* __restrict__ ei,
                        const float* __restrict__ asp, const float* __restrict__ actx,
                        const float* __restrict__ alat,
                        const float* __restrict__ wsp, const float* __restrict__ wctx,
                        const float* __restrict__ wlat, int N, int E) {
    int e = blockIdx.x * blockDim.x + threadIdx.x;
    if (e >= E) return;
    int t = ei[E + e];
    float e0 = asp[e] * wsp[e];
    float e1 = actx[e] * wctx[e];
    float e2 = alat[e] * wlat[e];
    atomicAdd(&g_deg[t],         e0);
    atomicAdd(&g_deg[N + t],     e1);
    atomicAdd(&g_deg[2 * N + t], e2);
    atomicAdd(&g_count[t], 1);
}

// ---------------- block scans ----------------
__device__ __forceinline__ int block_incl_scan(int v, int* s) {
    int tid = threadIdx.x;
    s[tid] = v;
    __syncthreads();
    #pragma unroll
    for (int o = 1; o < 256; o <<= 1) {
        int t = (tid >= o) ? s[tid - o] : 0;
        __syncthreads();
        s[tid] += t;
        __syncthreads();
    }
    return s[tid];
}

__global__ void k_scan1(int N) {
    __shared__ int s[256];
    int i = blockIdx.x * 256 + threadIdx.x;
    int v = (i < N) ? g_count[i] : 0;
    block_incl_scan(v, s);
    if (threadIdx.x == 255) g_blksum[blockIdx.x] = s[255];
}

__global__ void k_scan2(int nblk, int E, int N) {
    __shared__ int s[256];
    int tid = threadIdx.x;
    int v = (tid < nblk) ? g_blksum[tid] : 0;
    int inc = block_incl_scan(v, s);
    g_blkoff[tid] = inc - v;
    if (tid == 0) g_rowstart[N] = E;
}

__global__ void k_scan3(int N) {
    __shared__ int s[256];
    int i = blockIdx.x * 256 + threadIdx.x;
    int v = (i < N) ? g_count[i] : 0;
    int inc = block_incl_scan(v, s);
    if (i < N) {
        int excl = inc - v + g_blkoff[blockIdx.x];
        g_rowstart[i] = excl;
        g_cursor[i] = excl;
    }
}

// ---------------- edge pass 2: scatter edges into CSR slots ----------------
__global__ void k_edge2(const int* __restrict__ ei,
                        const float* __restrict__ asp, const float* __restrict__ actx,
                        const float* __restrict__ alat,
                        const float* __restrict__ wsp, const float* __restrict__ wctx,
                        const float* __restrict__ wlat, int N, int E) {
    int e = blockIdx.x * blockDim.x + threadIdx.x;
    if (e >= E) return;
    int t = ei[E + e];
    int s = ei[e];
    int p = atomicAdd(&g_cursor[t], 1);
    g_srcp[p] = s;
    g_effp[p]         = asp[e]  * wsp[e];
    g_effp[E + p]     = actx[e] * wctx[e];
    g_effp[2 * E + p] = alat[e] * wlat[e];
}

// ---------------- per-layer: dinv = clip(deg,1e-6)^p ----------------
__global__ void k_dinv(const float* __restrict__ deg_power, int l, int N) {
    int i = blockIdx.x * blockDim.x + threadIdx.x;
    if (i >= 3 * N) return;
    int c = i / N;
    float p = deg_power[l * 3 + c];
    float d = fmaxf(g_deg[i], 1e-6f);
    g_dinv[i] = powf(d, p);
}

// ---------------- aggregate: one block per target node ----------------
__global__ void k_agg(const float* __restrict__ x, int use_h, int N, int E) {
    int t = blockIdx.x;
    if (t >= N) return;
    const float* __restrict__ X = use_h ? g_h : x;
    int tid = threadIdx.x;   // 128
    int s = g_rowstart[t];
    int eend = g_rowstart[t + 1];
    float dt0 = g_dinv[t], dt1 = g_dinv[N + t], dt2 = g_dinv[2 * N + t];
    float a0 = 0.f, a1 = 0.f, a2 = 0.f;
    for (int p = s; p < eend; p++) {
        int sid = __ldg(&g_srcp[p]);
        float n0 = __ldg(&g_effp[p])         * dt0 * __ldg(&g_dinv[sid]);
        float n1 = __ldg(&g_effp[E + p])     * dt1 * __ldg(&g_dinv[N + sid]);
        float n2 = __ldg(&g_effp[2 * E + p]) * dt2 * __ldg(&g_dinv[2 * N + sid]);
        float xv = __ldg(&X[sid * D + tid]);
        a0 = fmaf(n0, xv, a0);
        a1 = fmaf(n1, xv, a1);
        a2 = fmaf(n2, xv, a2);
    }
    g_agg[t * D + tid]               = a0;
    g_agg[N * D + t * D + tid]       = a1;
    g_agg[2 * N * D + t * D + tid]   = a2;
}

// ---------------- prepB: split weights to bf16 hi/lo, transposed [l][c][n][k] ----------------
__global__ void k_prepB(const float* __restrict__ Wself, const float* __restrict__ W3, int L) {
    int idx = blockIdx.x * blockDim.x + threadIdx.x;
    int total = L * 4 * D * D;
    if (idx >= total) return;
    int l  = idx / (4 * D * D);
    int r  = idx % (4 * D * D);
    int c  = r / (D * D);
    int nk = r % (D * D);
    int n  = nk >> 7;
    int k  = nk & 127;
    float v = (c == 0) ? Wself[l * D * D + k * D + n]
                       : W3[((l * 3) + (c - 1)) * D * D + k * D + n];
    __nv_bfloat16 hi = __float2bfloat16(v);
    float hf = __bfloat162float(hi);
    __nv_bfloat16 lo = __float2bfloat16(v - hf);
    g_Bhi[idx] = hi;
    g_Blo[idx] = lo;
}

// ---------------- warp-MMA GEMM (HMMA m16n8k16 bf16, fp32 acc) ----------------
// out[128m x 128n] per block. A = [X|agg0|agg1|agg2] split bf16 inline,
// B precomputed split bf16 [n][k]. acc += Ahi*Bhi + Ahi*Blo + Alo*Bhi.
constexpr int APITCH = 72;   // bf16 elements per smem row (padded; conflict-free frags)
constexpr int OFF_A_HI = 0;
constexpr int OFF_A_LO = 128 * APITCH * 2;            // 18432
constexpr int OFF_B_HI = 2 * 128 * APITCH * 2;        // 36864
constexpr int OFF_B_LO = 3 * 128 * APITCH * 2;        // 55296
constexpr int SMEM_GEMM = 4 * 128 * APITCH * 2;       // 73728

__device__ __forceinline__ void mma16816(float* d, const uint32_t* a, const uint32_t* b) {
    asm volatile("mma.sync.aligned.m16n8k16.row.col.f32.bf16.bf16.f32 "
        "{%0,%1,%2,%3}, {%4,%5,%6,%7}, {%8,%9}, {%0,%1,%2,%3};"
        : "+f"(d[0]), "+f"(d[1]), "+f"(d[2]), "+f"(d[3])
        : "r"(a[0]), "r"(a[1]), "r"(a[2]), "r"(a[3]), "r"(b[0]), "r"(b[1]));
}

__global__ void __launch_bounds__(256, 2)
k_gemm_mma(const float* __restrict__ x, int use_h, int layer,
           const float* __restrict__ bias, float* __restrict__ dout, int last, int N) {
    extern __shared__ char smem[];
    __nv_bfloat16* Ah = (__nv_bfloat16*)(smem + OFF_A_HI);
    __nv_bfloat16* Al = (__nv_bfloat16*)(smem + OFF_A_LO);
    __nv_bfloat16* Bh = (__nv_bfloat16*)(smem + OFF_B_HI);
    __nv_bfloat16* Bl = (__nv_bfloat16*)(smem + OFF_B_LO);

    int tid = threadIdx.x;
    int wid = tid >> 5;
    int lane = tid & 31;
    int group = lane >> 2;        // 0..7
    int tg = lane & 3;            // 0..3
    int warp_m = wid >> 2;        // 0..1 -> 64 rows each
    int warp_n = wid & 3;         // 0..3 -> 32 cols each
    int bm0 = blockIdx.x * 128;

    const float* Ap0 = use_h ? g_h : x;
    const float* Ap[4] = { Ap0, g_agg, g_agg + (size_t)N * D, g_agg + 2 * (size_t)N * D };
    const __nv_bfloat16* BhiL = g_Bhi + (size_t)layer * 4 * D * D;
    const __nv_bfloat16* BloL = g_Blo + (size_t)layer * 4 * D * D;

    float acc[4][4][4];
    #pragma unroll
    for (int mt = 0; mt < 4; mt++)
        #pragma unroll
        for (int nt = 0; nt < 4; nt++)
            #pragma unroll
            for (int j = 0; j < 4; j++) acc[mt][nt][j] = 0.f;

    for (int chunk = 0; chunk < 8; chunk++) {
        int c = chunk >> 1;
        int koff = (chunk & 1) * 64;
        const float* __restrict__ A = Ap[c];

        // ---- stage A: 128 rows x 64 k fp32 -> split bf16 hi/lo ----
        #pragma unroll
        for (int i = 0; i < 8; i++) {
            int idx = tid + i * 256;          // < 2048
            int row = idx >> 4;
            int q = idx & 15;                 // k group of 4
            int gr = bm0 + row;
            float4 v = make_float4(0.f, 0.f, 0.f, 0.f);
            if (gr < N) v = *(const float4*)(A + (size_t)gr * D + koff + q * 4);
            __nv_bfloat16 h0 = __float2bfloat16(v.x);
            __nv_bfloat16 h1 = __float2bfloat16(v.y);
            __nv_bfloat16 h2 = __float2bfloat16(v.z);
            __nv_bfloat16 h3 = __float2bfloat16(v.w);
            __nv_bfloat16 l0 = __float2bfloat16(v.x - __bfloat162float(h0));
            __nv_bfloat16 l1 = __float2bfloat16(v.y - __bfloat162float(h1));
            __nv_bfloat16 l2 = __float2bfloat16(v.z - __bfloat162float(h2));
            __nv_bfloat16 l3 = __float2bfloat16(v.w - __bfloat162float(h3));
            uint32_t hp0 = ((uint32_t)__bfloat16_as_ushort(h1) << 16) | __bfloat16_as_ushort(h0);
            uint32_t hp1 = ((uint32_t)__bfloat16_as_ushort(h3) << 16) | __bfloat16_as_ushort(h2);
            uint32_t lp0 = ((uint32_t)__bfloat16_as_ushort(l1) << 16) | __bfloat16_as_ushort(l0);
            uint32_t lp1 = ((uint32_t)__bfloat16_as_ushort(l3) << 16) | __bfloat16_as_ushort(l2);
            int so = row * APITCH + q * 4;
            *(uint2*)(Ah + so) = make_uint2(hp0, hp1);
            *(uint2*)(Al + so) = make_uint2(lp0, lp1);
        }
        // ---- stage B: 128 n x 64 k bf16 hi/lo ----
        const __nv_bfloat16* bh = BhiL + c * D * D + koff;
        const __nv_bfloat16* bl = BloL + c * D * D + koff;
        #pragma unroll
        for (int i = 0; i < 4; i++) {
            int idx = tid + i * 256;          // < 1024
            int row = idx >> 3;
            int q = idx & 7;                  // k group of 8
            int so = row * APITCH + q * 8;
            *(uint4*)(Bh + so) = *(const uint4*)(bh + row * D + q * 8);
            *(uint4*)(Bl + so) = *(const uint4*)(bl + row * D + q * 8);
        }
        __syncthreads();

        // ---- compute: 4 k16 steps ----
        #pragma unroll
        for (int s = 0; s < 4; s++) {
            int ks = s * 16;
            // B fragments for 4 n-tiles (hi & lo)
            uint32_t bhf[4][2], blf[4][2];
            #pragma unroll
            for (int nt = 0; nt < 4; nt++) {
                int n0 = warp_n * 32 + nt * 8 + group;
                int o = n0 * APITCH + ks + tg * 2;
                bhf[nt][0] = *(const uint32_t*)(Bh + o);
                bhf[nt][1] = *(const uint32_t*)(Bh + o + 8);
                blf[nt][0] = *(const uint32_t*)(Bl + o);
                blf[nt][1] = *(const uint32_t*)(Bl + o + 8);
            }
            #pragma unroll
            for (int mt = 0; mt < 4; mt++) {
                int r0 = warp_m * 64 + mt * 16 + group;
                int o = r0 * APITCH + ks + tg * 2;
                uint32_t ahf[4], alf[4];
                ahf[0] = *(const uint32_t*)(Ah + o);
                ahf[1] = *(const uint32_t*)(Ah + o + 8 * APITCH);
                ahf[2] = *(const uint32_t*)(Ah + o + 8);
                ahf[3] = *(const uint32_t*)(Ah + o + 8 * APITCH + 8);
                alf[0] = *(const uint32_t*)(Al + o);
                alf[1] = *(const uint32_t*)(Al + o + 8 * APITCH);
                alf[2] = *(const uint32_t*)(Al + o + 8);
                alf[3] = *(const uint32_t*)(Al + o + 8 * APITCH + 8);
                #pragma unroll
                for (int nt = 0; nt < 4; nt++) {
                    mma16816(acc[mt][nt], ahf, bhf[nt]);
                    mma16816(acc[mt][nt], ahf, blf[nt]);
                    mma16816(acc[mt][nt], alf, bhf[nt]);
                }
            }
        }
        __syncthreads();
    }

    // ---- epilogue: bias + store ----
    float* outbuf = last ? dout : g_h;
    #pragma unroll
    for (int mt = 0; mt < 4; mt++) {
        int r0 = bm0 + warp_m * 64 + mt * 16 + group;
        #pragma unroll
        for (int nt = 0; nt < 4; nt++) {
            int c0 = warp_n * 32 + nt * 8 + tg * 2;
            float b0 = bias[c0], b1 = bias[c0 + 1];
            if (r0 < N) {
                float2 o = make_float2(acc[mt][nt][0] + b0, acc[mt][nt][1] + b1);
                *(float2*)(outbuf + (size_t)r0 * D + c0) = o;
            }
            if (r0 + 8 < N) {
                float2 o = make_float2(acc[mt][nt][2] + b0, acc[mt][nt][3] + b1);
                *(float2*)(outbuf + (size_t)(r0 + 8) * D + c0) = o;
            }
        }
    }
}

// ---------------- LayerNorm + ReLU over g_h (warp per row) ----------------
__global__ void k_lnrelu(const float* __restrict__ lng, const float* __restrict__ lnb, int N) {
    int wid = threadIdx.x >> 5;
    int lane = threadIdx.x & 31;
    int row = blockIdx.x * 8 + wid;
    if (row >= N) return;
    float4 v = *(float4*)(g_h + (size_t)row * D + lane * 4);
    float s = v.x + v.y + v.z + v.w;
    float sq = v.x * v.x + v.y * v.y + v.z * v.z + v.w * v.w;
    #pragma unroll
    for (int o = 16; o > 0; o >>= 1) {
        s  += __shfl_xor_sync(0xffffffffu, s, o);
        sq += __shfl_xor_sync(0xffffffffu, sq, o);
    }
    float mu = s * (1.0f / 128.0f);
    float var = sq * (1.0f / 128.0f) - mu * mu;
    float rs = rsqrtf(var + 1e-5f);
    float4 g = *(const float4*)(lng + lane * 4);
    float4 b = *(const float4*)(lnb + lane * 4);
    float4 o;
    o.x = fmaxf((v.x - mu) * rs * g.x + b.x, 0.f);
    o.y = fmaxf((v.y - mu) * rs * g.y + b.y, 0.f);
    o.z = fmaxf((v.z - mu) * rs * g.z + b.z, 0.f);
    o.w = fmaxf((v.w - mu) * rs * g.w + b.w, 0.f);
    *(float4*)(g_h + (size_t)row * D + lane * 4) = o;
}

// ---------------- launch ----------------
extern "C" void kernel_launch(void* const* d_in, const int* in_sizes, int n_in,
                              void* d_out, int out_size) {
    const float* x    = (const float*)d_in[0];
    const int*   ei   = (const int*)d_in[1];
    const float* asp  = (const float*)d_in[2];
    const float* actx = (const float*)d_in[3];
    const float* alat = (const float*)d_in[4];
    const float* wsp  = (const float*)d_in[5];
    const float* wctx = (const float*)d_in[6];
    const float* wlat = (const float*)d_in[7];
    const float* W3   = (const float*)d_in[8];   // [L,3,D,D]
    const float* Wslf = (const float*)d_in[9];   // [L,D,D]
    const float* bias = (const float*)d_in[10];  // [L,D]
    const float* degp = (const float*)d_in[11];  // [L,3]
    const float* lng  = (const float*)d_in[12];
    const float* lnb  = (const float*)d_in[13];
    float* out = (float*)d_out;

    int N = in_sizes[0] / D;
    int E = in_sizes[2];
    int L = in_sizes[10] / D;
    int nblk = (N + 255) / 256;

    cudaFuncSetAttribute(k_gemm_mma, cudaFuncAttributeMaxDynamicSharedMemorySize, SMEM_GEMM);

    k_init<<<(3 * N + 255) / 256, 256>>>(N);
    k_edge1<<<(E + 255) / 256, 256>>>(ei, asp, actx, alat, wsp, wctx, wlat, N, E);
    k_scan1<<<nblk, 256>>>(N);
    k_scan2<<<1, 256>>>(nblk, E, N);
    k_scan3<<<nblk, 256>>>(N);
    k_edge2<<<(E + 255) / 256, 256>>>(ei, asp, actx, alat, wsp, wctx, wlat, N, E);
    k_prepB<<<(L * 4 * D * D + 255) / 256, 256>>>(Wslf, W3, L);

    int gemm_grid = (N + 127) / 128;
    for (int l = 0; l < L; l++) {
        int use_h = (l > 0) ? 1 : 0;
        int last = (l == L - 1) ? 1 : 0;
        k_dinv<<<(3 * N + 255) / 256, 256>>>(degp, l, N);
        k_agg<<<N, 128>>>(x, use_h, N, E);
        k_gemm_mma<<<gemm_grid, 256, SMEM_GEMM>>>(x, use_h, l, bias + l * D, out, last, N);
        if (!last) k_lnrelu<<<(N + 7) / 8, 256>>>(lng, lnb, N);
    }
}

// round 5
// speedup vs baseline: 2.0906x; 1.0418x over previous
#include <cuda_runtime.h>
#include <cuda_bf16.h>
#include <cstdint>

#define D 128
constexpr int MAXN = 50048;
constexpr int MAXE = 1000192;

// ---------------- scratch (static device globals; no allocation) ----------------
__device__ float  g_deg  [3 * MAXN];
__device__ float  g_dinv [3 * MAXN];
__device__ int    g_count[MAXN];
__device__ int    g_rowstart[MAXN + 1];
__device__ int    g_cursor[MAXN];
__device__ float4 g_eff4 [MAXE];          // (e0, e1, e2, sid-as-int-bits) at CSR position
__device__ float4 g_m4   [MAXE];          // (e0*dinv0[s], e1*dinv1[s], e2*dinv2[s], sid)
__device__ float  g_agg  [3 * MAXN * D];  // [c][N][D]
__device__ float  g_h    [MAXN * D];      // inter-layer activations
__device__ int    g_blksum[256];
__device__ int    g_blkoff[256];
// split-bf16 weights, transposed to [l][c][n][k] (B as N x K, K-major)
__device__ __nv_bfloat16 g_Bhi[2 * 4 * D * D];
__device__ __nv_bfloat16 g_Blo[2 * 4 * D * D];

// ---------------- init: count = 0 ----------------
__global__ void k_init(int N) {
    int i = blockIdx.x * blockDim.x + threadIdx.x;
    if (i < N) g_count[i] = 0;
}

// ---------------- edge pass 1: target histogram only (1 int atomic/edge) ----------------
__global__ void k_edge1(const int* __restrict__ ei, int N, int E) {
    int e = blockIdx.x * blockDim.x + threadIdx.x;
    if (e >= E) return;
    atomicAdd(&g_count[ei[E + e]], 1);
}

// ---------------- block scans ----------------
__device__ __forceinline__ int block_incl_scan(int v, int* s) {
    int tid = threadIdx.x;
    s[tid] = v;
    __syncthreads();
    #pragma unroll
    for (int o = 1; o < 256; o <<= 1) {
        int t = (tid >= o) ? s[tid - o] : 0;
        __syncthreads();
        s[tid] += t;
        __syncthreads();
    }
    return s[tid];
}

__global__ void k_scan1(int N) {
    __shared__ int s[256];
    int i = blockIdx.x * 256 + threadIdx.x;
    int v = (i < N) ? g_count[i] : 0;
    block_incl_scan(v, s);
    if (threadIdx.x == 255) g_blksum[blockIdx.x] = s[255];
}

__global__ void k_scan2(int nblk, int E, int N) {
    __shared__ int s[256];
    int tid = threadIdx.x;
    int v = (tid < nblk) ? g_blksum[tid] : 0;
    int inc = block_incl_scan(v, s);
    g_blkoff[tid] = inc - v;
    if (tid == 0) g_rowstart[N] = E;
}

__global__ void k_scan3(int N) {
    __shared__ int s[256];
    int i = blockIdx.x * 256 + threadIdx.x;
    int v = (i < N) ? g_count[i] : 0;
    int inc = block_incl_scan(v, s);
    if (i < N) {
        int excl = inc - v + g_blkoff[blockIdx.x];
        g_rowstart[i] = excl;
        g_cursor[i] = excl;
    }
}

// ---------------- edge pass 2: scatter (eff0,eff1,eff2,sid) into CSR slots ----------------
__global__ void k_edge2(const int* __restrict__ ei,
                        const float* __restrict__ asp, const float* __restrict__ actx,
                        const float* __restrict__ alat,
                        const float* __restrict__ wsp, const float* __restrict__ wctx,
                        const float* __restrict__ wlat, int N, int E) {
    int e = blockIdx.x * blockDim.x + threadIdx.x;
    if (e >= E) return;
    int t = ei[E + e];
    int s = ei[e];
    int p = atomicAdd(&g_cursor[t], 1);
    float4 v;
    v.x = asp[e]  * wsp[e];
    v.y = actx[e] * wctx[e];
    v.z = alat[e] * wlat[e];
    v.w = __int_as_float(s);
    g_eff4[p] = v;
}

// ---------------- degrees from CSR rows (no float atomics); warp per node ----------------
__global__ void k_deg(int N) {
    int gw = (blockIdx.x * blockDim.x + threadIdx.x) >> 5;
    int lane = threadIdx.x & 31;
    if (gw >= N) return;
    int s = g_rowstart[gw], e = g_rowstart[gw + 1];
    float d0 = 0.f, d1 = 0.f, d2 = 0.f;
    for (int p = s + lane; p < e; p += 32) {
        float4 v = __ldg(&g_eff4[p]);
        d0 += v.x; d1 += v.y; d2 += v.z;
    }
    #pragma unroll
    for (int o = 16; o > 0; o >>= 1) {
        d0 += __shfl_xor_sync(0xffffffffu, d0, o);
        d1 += __shfl_xor_sync(0xffffffffu, d1, o);
        d2 += __shfl_xor_sync(0xffffffffu, d2, o);
    }
    if (lane == 0) {
        g_deg[gw]         = 1.f + d0;
        g_deg[N + gw]     = 1.f + d1;
        g_deg[2 * N + gw] = 1.f + d2;
    }
}

// ---------------- per-layer: dinv = clip(deg,1e-6)^p ----------------
__global__ void k_dinv(const float* __restrict__ deg_power, int l, int N) {
    int i = blockIdx.x * blockDim.x + threadIdx.x;
    if (i >= 3 * N) return;
    int c = i / N;
    float p = deg_power[l * 3 + c];
    float d = fmaxf(g_deg[i], 1e-6f);
    g_dinv[i] = powf(d, p);
}

// ---------------- per-layer: m_c = eff_c * dinv_c[src], packed with sid ----------------
__global__ void k_prep_m(int N, int E) {
    int p = blockIdx.x * blockDim.x + threadIdx.x;
    if (p >= E) return;
    float4 e4 = __ldg(&g_eff4[p]);
    int sid = __float_as_int(e4.w);
    float4 m;
    m.x = e4.x * __ldg(&g_dinv[sid]);
    m.y = e4.y * __ldg(&g_dinv[N + sid]);
    m.z = e4.z * __ldg(&g_dinv[2 * N + sid]);
    m.w = e4.w;
    g_m4[p] = m;
}

// ---------------- aggregate: block per target node, unrolled x4 for MLP ----------------
__global__ void __launch_bounds__(128, 8)
k_agg(const float* __restrict__ x, int use_h, int N) {
    int t = blockIdx.x;
    if (t >= N) return;
    const float* __restrict__ X = use_h ? g_h : x;
    int tid = threadIdx.x;   // 128
    int s = g_rowstart[t];
    int e = g_rowstart[t + 1];
    float a0 = 0.f, a1 = 0.f, a2 = 0.f;
    int p = s;
    for (; p + 4 <= e; p += 4) {
        float4 m0 = __ldg(&g_m4[p]);
        float4 m1 = __ldg(&g_m4[p + 1]);
        float4 m2 = __ldg(&g_m4[p + 2]);
        float4 m3 = __ldg(&g_m4[p + 3]);
        float x0 = __ldg(&X[(size_t)__float_as_int(m0.w) * D + tid]);
        float x1 = __ldg(&X[(size_t)__float_as_int(m1.w) * D + tid]);
        float x2 = __ldg(&X[(size_t)__float_as_int(m2.w) * D + tid]);
        float x3 = __ldg(&X[(size_t)__float_as_int(m3.w) * D + tid]);
        a0 = fmaf(m0.x, x0, a0); a1 = fmaf(m0.y, x0, a1); a2 = fmaf(m0.z, x0, a2);
        a0 = fmaf(m1.x, x1, a0); a1 = fmaf(m1.y, x1, a1); a2 = fmaf(m1.z, x1, a2);
        a0 = fmaf(m2.x, x2, a0); a1 = fmaf(m2.y, x2, a1); a2 = fmaf(m2.z, x2, a2);
        a0 = fmaf(m3.x, x3, a0); a1 = fmaf(m3.y, x3, a1); a2 = fmaf(m3.z, x3, a2);
    }
    for (; p < e; p++) {
        float4 m = __ldg(&g_m4[p]);
        float xv = __ldg(&X[(size_t)__float_as_int(m.w) * D + tid]);
        a0 = fmaf(m.x, xv, a0);
        a1 = fmaf(m.y, xv, a1);
        a2 = fmaf(m.z, xv, a2);
    }
    float dt0 = g_dinv[t], dt1 = g_dinv[N + t], dt2 = g_dinv[2 * N + t];
    g_agg[(size_t)t * D + tid]                       = a0 * dt0;
    g_agg[(size_t)N * D + (size_t)t * D + tid]       = a1 * dt1;
    g_agg[2 * (size_t)N * D + (size_t)t * D + tid]   = a2 * dt2;
}

// ---------------- prepB: split weights to bf16 hi/lo, transposed [l][c][n][k] ----------------
__global__ void k_prepB(const float* __restrict__ Wself, const float* __restrict__ W3, int L) {
    int idx = blockIdx.x * blockDim.x + threadIdx.x;
    int total = L * 4 * D * D;
    if (idx >= total) return;
    int l  = idx / (4 * D * D);
    int r  = idx % (4 * D * D);
    int c  = r / (D * D);
    int nk = r % (D * D);
    int n  = nk >> 7;
    int k  = nk & 127;
    float v = (c == 0) ? Wself[l * D * D + k * D + n]
                       : W3[((l * 3) + (c - 1)) * D * D + k * D + n];
    __nv_bfloat16 hi = __float2bfloat16(v);
    float hf = __bfloat162float(hi);
    __nv_bfloat16 lo = __float2bfloat16(v - hf);
    g_Bhi[idx] = hi;
    g_Blo[idx] = lo;
}

// ---------------- warp-MMA GEMM (HMMA m16n8k16 bf16, fp32 acc) ----------------
constexpr int APITCH = 72;
constexpr int OFF_A_HI = 0;
constexpr int OFF_A_LO = 128 * APITCH * 2;
constexpr int OFF_B_HI = 2 * 128 * APITCH * 2;
constexpr int OFF_B_LO = 3 * 128 * APITCH * 2;
constexpr int SMEM_GEMM = 4 * 128 * APITCH * 2;

__device__ __forceinline__ void mma16816(float* d, const uint32_t* a, const uint32_t* b) {
    asm volatile("mma.sync.aligned.m16n8k16.row.col.f32.bf16.bf16.f32 "
        "{%0,%1,%2,%3}, {%4,%5,%6,%7}, {%8,%9}, {%0,%1,%2,%3};"
        : "+f"(d[0]), "+f"(d[1]), "+f"(d[2]), "+f"(d[3])
        : "r"(a[0]), "r"(a[1]), "r"(a[2]), "r"(a[3]), "r"(b[0]), "r"(b[1]));
}

__global__ void __launch_bounds__(256, 2)
k_gemm_mma(const float* __restrict__ x, int use_h, int layer,
           const float* __restrict__ bias, float* __restrict__ dout, int last, int N) {
    extern __shared__ char smem[];
    __nv_bfloat16* Ah = (__nv_bfloat16*)(smem + OFF_A_HI);
    __nv_bfloat16* Al = (__nv_bfloat16*)(smem + OFF_A_LO);
    __nv_bfloat16* Bh = (__nv_bfloat16*)(smem + OFF_B_HI);
    __nv_bfloat16* Bl = (__nv_bfloat16*)(smem + OFF_B_LO);

    int tid = threadIdx.x;
    int wid = tid >> 5;
    int lane = tid & 31;
    int group = lane >> 2;
    int tg = lane & 3;
    int warp_m = wid >> 2;
    int warp_n = wid & 3;
    int bm0 = blockIdx.x * 128;

    const float* Ap0 = use_h ? g_h : x;
    const float* Ap[4] = { Ap0, g_agg, g_agg + (size_t)N * D, g_agg + 2 * (size_t)N * D };
    const __nv_bfloat16* BhiL = g_Bhi + (size_t)layer * 4 * D * D;
    const __nv_bfloat16* BloL = g_Blo + (size_t)layer * 4 * D * D;

    float acc[4][4][4];
    #pragma unroll
    for (int mt = 0; mt < 4; mt++)
        #pragma unroll
        for (int nt = 0; nt < 4; nt++)
            #pragma unroll
            for (int j = 0; j < 4; j++) acc[mt][nt][j] = 0.f;

    for (int chunk = 0; chunk < 8; chunk++) {
        int c = chunk >> 1;
        int koff = (chunk & 1) * 64;
        const float* __restrict__ A = Ap[c];

        #pragma unroll
        for (int i = 0; i < 8; i++) {
            int idx = tid + i * 256;
            int row = idx >> 4;
            int q = idx & 15;
            int gr = bm0 + row;
            float4 v = make_float4(0.f, 0.f, 0.f, 0.f);
            if (gr < N) v = *(const float4*)(A + (size_t)gr * D + koff + q * 4);
            __nv_bfloat16 h0 = __float2bfloat16(v.x);
            __nv_bfloat16 h1 = __float2bfloat16(v.y);
            __nv_bfloat16 h2 = __float2bfloat16(v.z);
            __nv_bfloat16 h3 = __float2bfloat16(v.w);
            __nv_bfloat16 l0 = __float2bfloat16(v.x - __bfloat162float(h0));
            __nv_bfloat16 l1 = __float2bfloat16(v.y - __bfloat162float(h1));
            __nv_bfloat16 l2 = __float2bfloat16(v.z - __bfloat162float(h2));
            __nv_bfloat16 l3 = __float2bfloat16(v.w - __bfloat162float(h3));
            uint32_t hp0 = ((uint32_t)__bfloat16_as_ushort(h1) << 16) | __bfloat16_as_ushort(h0);
            uint32_t hp1 = ((uint32_t)__bfloat16_as_ushort(h3) << 16) | __bfloat16_as_ushort(h2);
            uint32_t lp0 = ((uint32_t)__bfloat16_as_ushort(l1) << 16) | __bfloat16_as_ushort(l0);
            uint32_t lp1 = ((uint32_t)__bfloat16_as_ushort(l3) << 16) | __bfloat16_as_ushort(l2);
            int so = row * APITCH + q * 4;
            *(uint2*)(Ah + so) = make_uint2(hp0, hp1);
            *(uint2*)(Al + so) = make_uint2(lp0, lp1);
        }
        const __nv_bfloat16* bh = BhiL + c * D * D + koff;
        const __nv_bfloat16* bl = BloL + c * D * D + koff;
        #pragma unroll
        for (int i = 0; i < 4; i++) {
            int idx = tid + i * 256;
            int row = idx >> 3;
            int q = idx & 7;
            int so = row * APITCH + q * 8;
            *(uint4*)(Bh + so) = *(const uint4*)(bh + row * D + q * 8);
            *(uint4*)(Bl + so) = *(const uint4*)(bl + row * D + q * 8);
        }
        __syncthreads();

        #pragma unroll
        for (int s = 0; s < 4; s++) {
            int ks = s * 16;
            uint32_t bhf[4][2], blf[4][2];
            #pragma unroll
            for (int nt = 0; nt < 4; nt++) {
                int n0 = warp_n * 32 + nt * 8 + group;
                int o = n0 * APITCH + ks + tg * 2;
                bhf[nt][0] = *(const uint32_t*)(Bh + o);
                bhf[nt][1] = *(const uint32_t*)(Bh + o + 8);
                blf[nt][0] = *(const uint32_t*)(Bl + o);
                blf[nt][1] = *(const uint32_t*)(Bl + o + 8);
            }
            #pragma unroll
            for (int mt = 0; mt < 4; mt++) {
                int r0 = warp_m * 64 + mt * 16 + group;
                int o = r0 * APITCH + ks + tg * 2;
                uint32_t ahf[4], alf[4];
                ahf[0] = *(const uint32_t*)(Ah + o);
                ahf[1] = *(const uint32_t*)(Ah + o + 8 * APITCH);
                ahf[2] = *(const uint32_t*)(Ah + o + 8);
                ahf[3] = *(const uint32_t*)(Ah + o + 8 * APITCH + 8);
                alf[0] = *(const uint32_t*)(Al + o);
                alf[1] = *(const uint32_t*)(Al + o + 8 * APITCH);
                alf[2] = *(const uint32_t*)(Al + o + 8);
                alf[3] = *(const uint32_t*)(Al + o + 8 * APITCH + 8);
                #pragma unroll
                for (int nt = 0; nt < 4; nt++) {
                    mma16816(acc[mt][nt], ahf, bhf[nt]);
                    mma16816(acc[mt][nt], ahf, blf[nt]);
                    mma16816(acc[mt][nt], alf, bhf[nt]);
                }
            }
        }
        __syncthreads();
    }

    float* outbuf = last ? dout : g_h;
    #pragma unroll
    for (int mt = 0; mt < 4; mt++) {
        int r0 = bm0 + warp_m * 64 + mt * 16 + group;
        #pragma unroll
        for (int nt = 0; nt < 4; nt++) {
            int c0 = warp_n * 32 + nt * 8 + tg * 2;
            float b0 = bias[c0], b1 = bias[c0 + 1];
            if (r0 < N) {
                float2 o = make_float2(acc[mt][nt][0] + b0, acc[mt][nt][1] + b1);
                *(float2*)(outbuf + (size_t)r0 * D + c0) = o;
            }
            if (r0 + 8 < N) {
                float2 o = make_float2(acc[mt][nt][2] + b0, acc[mt][nt][3] + b1);
                *(float2*)(outbuf + (size_t)(r0 + 8) * D + c0) = o;
            }
        }
    }
}

// ---------------- LayerNorm + ReLU over g_h (warp per row) ----------------
__global__ void k_lnrelu(const float* __restrict__ lng, const float* __restrict__ lnb, int N) {
    int wid = threadIdx.x >> 5;
    int lane = threadIdx.x & 31;
    int row = blockIdx.x * 8 + wid;
    if (row >= N) return;
    float4 v = *(float4*)(g_h + (size_t)row * D + lane * 4);
    float s = v.x + v.y + v.z + v.w;
    float sq = v.x * v.x + v.y * v.y + v.z * v.z + v.w * v.w;
    #pragma unroll
    for (int o = 16; o > 0; o >>= 1) {
        s  += __shfl_xor_sync(0xffffffffu, s, o);
        sq += __shfl_xor_sync(0xffffffffu, sq, o);
    }
    float mu = s * (1.0f / 128.0f);
    float var = sq * (1.0f / 128.0f) - mu * mu;
    float rs = rsqrtf(var + 1e-5f);
    float4 g = *(const float4*)(lng + lane * 4);
    float4 b = *(const float4*)(lnb + lane * 4);
    float4 o;
    o.x = fmaxf((v.x - mu) * rs * g.x + b.x, 0.f);
    o.y = fmaxf((v.y - mu) * rs * g.y + b.y, 0.f);
    o.z = fmaxf((v.z - mu) * rs * g.z + b.z, 0.f);
    o.w = fmaxf((v.w - mu) * rs * g.w + b.w, 0.f);
    *(float4*)(g_h + (size_t)row * D + lane * 4) = o;
}

// ---------------- launch ----------------
extern "C" void kernel_launch(void* const* d_in, const int* in_sizes, int n_in,
                              void* d_out, int out_size) {
    const float* x    = (const float*)d_in[0];
    const int*   ei   = (const int*)d_in[1];
    const float* asp  = (const float*)d_in[2];
    const float* actx = (const float*)d_in[3];
    const float* alat = (const float*)d_in[4];
    const float* wsp  = (const float*)d_in[5];
    const float* wctx = (const float*)d_in[6];
    const float* wlat = (const float*)d_in[7];
    const float* W3   = (const float*)d_in[8];   // [L,3,D,D]
    const float* Wslf = (const float*)d_in[9];   // [L,D,D]
    const float* bias = (const float*)d_in[10];  // [L,D]
    const float* degp = (const float*)d_in[11];  // [L,3]
    const float* lng  = (const float*)d_in[12];
    const float* lnb  = (const float*)d_in[13];
    float* out = (float*)d_out;

    int N = in_sizes[0] / D;
    int E = in_sizes[2];
    int L = in_sizes[10] / D;
    int nblk = (N + 255) / 256;

    cudaFuncSetAttribute(k_gemm_mma, cudaFuncAttributeMaxDynamicSharedMemorySize, SMEM_GEMM);

    k_init<<<(N + 255) / 256, 256>>>(N);
    k_edge1<<<(E + 255) / 256, 256>>>(ei, N, E);
    k_scan1<<<nblk, 256>>>(N);
    k_scan2<<<1, 256>>>(nblk, E, N);
    k_scan3<<<nblk, 256>>>(N);
    k_edge2<<<(E + 255) / 256, 256>>>(ei, asp, actx, alat, wsp, wctx, wlat, N, E);
    k_deg<<<(N * 32 + 255) / 256, 256>>>(N);
    k_prepB<<<(L * 4 * D * D + 255) / 256, 256>>>(Wslf, W3, L);

    int gemm_grid = (N + 127) / 128;
    for (int l = 0; l < L; l++) {
        int use_h = (l > 0) ? 1 : 0;
        int last = (l == L - 1) ? 1 : 0;
        k_dinv<<<(3 * N + 255) / 256, 256>>>(degp, l, N);
        k_prep_m<<<(E + 255) / 256, 256>>>(N, E);
        k_agg<<<N, 128>>>(x, use_h, N);
        k_gemm_mma<<<gemm_grid, 256, SMEM_GEMM>>>(x, use_h, l, bias + l * D, out, last, N);
        if (!last) k_lnrelu<<<(N + 7) / 8, 256>>>(lng, lnb, N);
    }
}

// round 6
// speedup vs baseline: 2.9065x; 1.3903x over previous
#include <cuda_runtime.h>
#include <cuda_bf16.h>
#include <cstdint>

#define D 128
constexpr int MAXN = 50048;
constexpr int MAXE = 1000192;

// ---------------- scratch (static device globals; no allocation) ----------------
__device__ float  g_deg  [3 * MAXN];
__device__ float4 g_dinv4[MAXN];          // (d0, d1, d2, -) per node, current layer
__device__ int    g_count[MAXN];
__device__ int    g_rowstart[MAXN + 1];
__device__ int    g_cursor[MAXN];
__device__ float4 g_eff4 [MAXE];          // (e0, e1, e2, sid-as-int-bits) at CSR position
__device__ float  g_agg  [3 * MAXN * D];  // [c][N][D]
__device__ float  g_h    [MAXN * D];      // inter-layer activations
__device__ int    g_blksum[256];
__device__ int    g_blkoff[256];
// split-bf16 weights, transposed to [l][c][n][k] (B as N x K, K-major)
__device__ __nv_bfloat16 g_Bhi[2 * 4 * D * D];
__device__ __nv_bfloat16 g_Blo[2 * 4 * D * D];

// ---------------- init: count = 0 ----------------
__global__ void k_init(int N) {
    int i = blockIdx.x * blockDim.x + threadIdx.x;
    if (i < N) g_count[i] = 0;
}

// ---------------- edge pass 1: target histogram only (1 int atomic/edge) ----------------
__global__ void k_edge1(const int* __restrict__ ei, int N, int E) {
    int e = blockIdx.x * blockDim.x + threadIdx.x;
    if (e >= E) return;
    atomicAdd(&g_count[ei[E + e]], 1);
}

// ---------------- block scans ----------------
__device__ __forceinline__ int block_incl_scan(int v, int* s) {
    int tid = threadIdx.x;
    s[tid] = v;
    __syncthreads();
    #pragma unroll
    for (int o = 1; o < 256; o <<= 1) {
        int t = (tid >= o) ? s[tid - o] : 0;
        __syncthreads();
        s[tid] += t;
        __syncthreads();
    }
    return s[tid];
}

__global__ void k_scan1(int N) {
    __shared__ int s[256];
    int i = blockIdx.x * 256 + threadIdx.x;
    int v = (i < N) ? g_count[i] : 0;
    block_incl_scan(v, s);
    if (threadIdx.x == 255) g_blksum[blockIdx.x] = s[255];
}

__global__ void k_scan2(int nblk, int E, int N) {
    __shared__ int s[256];
    int tid = threadIdx.x;
    int v = (tid < nblk) ? g_blksum[tid] : 0;
    int inc = block_incl_scan(v, s);
    g_blkoff[tid] = inc - v;
    if (tid == 0) g_rowstart[N] = E;
}

__global__ void k_scan3(int N) {
    __shared__ int s[256];
    int i = blockIdx.x * 256 + threadIdx.x;
    int v = (i < N) ? g_count[i] : 0;
    int inc = block_incl_scan(v, s);
    if (i < N) {
        int excl = inc - v + g_blkoff[blockIdx.x];
        g_rowstart[i] = excl;
        g_cursor[i] = excl;
    }
}

// ---------------- edge pass 2: scatter (eff0,eff1,eff2,sid) into CSR slots ----------------
__global__ void k_edge2(const int* __restrict__ ei,
                        const float* __restrict__ asp, const float* __restrict__ actx,
                        const float* __restrict__ alat,
                        const float* __restrict__ wsp, const float* __restrict__ wctx,
                        const float* __restrict__ wlat, int N, int E) {
    int e = blockIdx.x * blockDim.x + threadIdx.x;
    if (e >= E) return;
    int t = ei[E + e];
    int s = ei[e];
    int p = atomicAdd(&g_cursor[t], 1);
    float4 v;
    v.x = asp[e]  * wsp[e];
    v.y = actx[e] * wctx[e];
    v.z = alat[e] * wlat[e];
    v.w = __int_as_float(s);
    g_eff4[p] = v;
}

// ---------------- degrees from CSR rows (no float atomics); warp per node ----------------
__global__ void k_deg(int N) {
    int gw = (blockIdx.x * blockDim.x + threadIdx.x) >> 5;
    int lane = threadIdx.x & 31;
    if (gw >= N) return;
    int s = g_rowstart[gw], e = g_rowstart[gw + 1];
    float d0 = 0.f, d1 = 0.f, d2 = 0.f;
    for (int p = s + lane; p < e; p += 32) {
        float4 v = __ldg(&g_eff4[p]);
        d0 += v.x; d1 += v.y; d2 += v.z;
    }
    #pragma unroll
    for (int o = 16; o > 0; o >>= 1) {
        d0 += __shfl_xor_sync(0xffffffffu, d0, o);
        d1 += __shfl_xor_sync(0xffffffffu, d1, o);
        d2 += __shfl_xor_sync(0xffffffffu, d2, o);
    }
    if (lane == 0) {
        g_deg[gw]         = 1.f + d0;
        g_deg[N + gw]     = 1.f + d1;
        g_deg[2 * N + gw] = 1.f + d2;
    }
}

// ---------------- per-layer: dinv4[n] = clip(deg,1e-6)^p for 3 channels ----------------
__global__ void k_dinv4(const float* __restrict__ deg_power, int l, int N) {
    int i = blockIdx.x * blockDim.x + threadIdx.x;
    if (i >= N) return;
    float p0 = deg_power[l * 3 + 0];
    float p1 = deg_power[l * 3 + 1];
    float p2 = deg_power[l * 3 + 2];
    float4 o;
    o.x = powf(fmaxf(g_deg[i],         1e-6f), p0);
    o.y = powf(fmaxf(g_deg[N + i],     1e-6f), p1);
    o.z = powf(fmaxf(g_deg[2 * N + i], 1e-6f), p2);
    o.w = 0.f;
    g_dinv4[i] = o;
}

// ---------------- aggregate: ONE WARP per target node; lane owns 4 features ----------------
__global__ void __launch_bounds__(256)
k_agg(const float* __restrict__ x, int use_h, int N) {
    int gw = (blockIdx.x * blockDim.x + threadIdx.x) >> 5;
    int lane = threadIdx.x & 31;
    if (gw >= N) return;
    const float* __restrict__ X = use_h ? g_h : x;
    int s = g_rowstart[gw];
    int e = g_rowstart[gw + 1];
    int fo = lane * 4;

    float4 a0 = make_float4(0.f, 0.f, 0.f, 0.f);
    float4 a1 = make_float4(0.f, 0.f, 0.f, 0.f);
    float4 a2 = make_float4(0.f, 0.f, 0.f, 0.f);

    int p = s;
    for (; p + 4 <= e; p += 4) {
        float4 e0 = __ldg(&g_eff4[p]);
        float4 e1 = __ldg(&g_eff4[p + 1]);
        float4 e2 = __ldg(&g_eff4[p + 2]);
        float4 e3 = __ldg(&g_eff4[p + 3]);
        int s0 = __float_as_int(e0.w);
        int s1 = __float_as_int(e1.w);
        int s2 = __float_as_int(e2.w);
        int s3 = __float_as_int(e3.w);
        float4 d0 = __ldg(&g_dinv4[s0]);
        float4 d1 = __ldg(&g_dinv4[s1]);
        float4 d2 = __ldg(&g_dinv4[s2]);
        float4 d3 = __ldg(&g_dinv4[s3]);
        float4 x0 = __ldg((const float4*)(X + (size_t)s0 * D + fo));
        float4 x1 = __ldg((const float4*)(X + (size_t)s1 * D + fo));
        float4 x2 = __ldg((const float4*)(X + (size_t)s2 * D + fo));
        float4 x3 = __ldg((const float4*)(X + (size_t)s3 * D + fo));
        float m;
        m = e0.x * d0.x; a0.x = fmaf(m, x0.x, a0.x); a0.y = fmaf(m, x0.y, a0.y); a0.z = fmaf(m, x0.z, a0.z); a0.w = fmaf(m, x0.w, a0.w);
        m = e0.y * d0.y; a1.x = fmaf(m, x0.x, a1.x); a1.y = fmaf(m, x0.y, a1.y); a1.z = fmaf(m, x0.z, a1.z); a1.w = fmaf(m, x0.w, a1.w);
        m = e0.z * d0.z; a2.x = fmaf(m, x0.x, a2.x); a2.y = fmaf(m, x0.y, a2.y); a2.z = fmaf(m, x0.z, a2.z); a2.w = fmaf(m, x0.w, a2.w);
        m = e1.x * d1.x; a0.x = fmaf(m, x1.x, a0.x); a0.y = fmaf(m, x1.y, a0.y); a0.z = fmaf(m, x1.z, a0.z); a0.w = fmaf(m, x1.w, a0.w);
        m = e1.y * d1.y; a1.x = fmaf(m, x1.x, a1.x); a1.y = fmaf(m, x1.y, a1.y); a1.z = fmaf(m, x1.z, a1.z); a1.w = fmaf(m, x1.w, a1.w);
        m = e1.z * d1.z; a2.x = fmaf(m, x1.x, a2.x); a2.y = fmaf(m, x1.y, a2.y); a2.z = fmaf(m, x1.z, a2.z); a2.w = fmaf(m, x1.w, a2.w);
        m = e2.x * d2.x; a0.x = fmaf(m, x2.x, a0.x); a0.y = fmaf(m, x2.y, a0.y); a0.z = fmaf(m, x2.z, a0.z); a0.w = fmaf(m, x2.w, a0.w);
        m = e2.y * d2.y; a1.x = fmaf(m, x2.x, a1.x); a1.y = fmaf(m, x2.y, a1.y); a1.z = fmaf(m, x2.z, a1.z); a1.w = fmaf(m, x2.w, a1.w);
        m = e2.z * d2.z; a2.x = fmaf(m, x2.x, a2.x); a2.y = fmaf(m, x2.y, a2.y); a2.z = fmaf(m, x2.z, a2.z); a2.w = fmaf(m, x2.w, a2.w);
        m = e3.x * d3.x; a0.x = fmaf(m, x3.x, a0.x); a0.y = fmaf(m, x3.y, a0.y); a0.z = fmaf(m, x3.z, a0.z); a0.w = fmaf(m, x3.w, a0.w);
        m = e3.y * d3.y; a1.x = fmaf(m, x3.x, a1.x); a1.y = fmaf(m, x3.y, a1.y); a1.z = fmaf(m, x3.z, a1.z); a1.w = fmaf(m, x3.w, a1.w);
        m = e3.z * d3.z; a2.x = fmaf(m, x3.x, a2.x); a2.y = fmaf(m, x3.y, a2.y); a2.z = fmaf(m, x3.z, a2.z); a2.w = fmaf(m, x3.w, a2.w);
    }
    for (; p < e; p++) {
        float4 ef = __ldg(&g_eff4[p]);
        int sid = __float_as_int(ef.w);
        float4 dv = __ldg(&g_dinv4[sid]);
        float4 xv = __ldg((const float4*)(X + (size_t)sid * D + fo));
        float m0 = ef.x * dv.x, m1 = ef.y * dv.y, m2 = ef.z * dv.z;
        a0.x = fmaf(m0, xv.x, a0.x); a0.y = fmaf(m0, xv.y, a0.y); a0.z = fmaf(m0, xv.z, a0.z); a0.w = fmaf(m0, xv.w, a0.w);
        a1.x = fmaf(m1, xv.x, a1.x); a1.y = fmaf(m1, xv.y, a1.y); a1.z = fmaf(m1, xv.z, a1.z); a1.w = fmaf(m1, xv.w, a1.w);
        a2.x = fmaf(m2, xv.x, a2.x); a2.y = fmaf(m2, xv.y, a2.y); a2.z = fmaf(m2, xv.z, a2.z); a2.w = fmaf(m2, xv.w, a2.w);
    }

    float4 dt = g_dinv4[gw];
    a0.x *= dt.x; a0.y *= dt.x; a0.z *= dt.x; a0.w *= dt.x;
    a1.x *= dt.y; a1.y *= dt.y; a1.z *= dt.y; a1.w *= dt.y;
    a2.x *= dt.z; a2.y *= dt.z; a2.z *= dt.z; a2.w *= dt.z;
    *(float4*)(g_agg + (size_t)gw * D + fo)                       = a0;
    *(float4*)(g_agg + (size_t)N * D + (size_t)gw * D + fo)       = a1;
    *(float4*)(g_agg + 2 * (size_t)N * D + (size_t)gw * D + fo)   = a2;
}

// ---------------- prepB: split weights to bf16 hi/lo, transposed [l][c][n][k] ----------------
__global__ void k_prepB(const float* __restrict__ Wself, const float* __restrict__ W3, int L) {
    int idx = blockIdx.x * blockDim.x + threadIdx.x;
    int total = L * 4 * D * D;
    if (idx >= total) return;
    int l  = idx / (4 * D * D);
    int r  = idx % (4 * D * D);
    int c  = r / (D * D);
    int nk = r % (D * D);
    int n  = nk >> 7;
    int k  = nk & 127;
    float v = (c == 0) ? Wself[l * D * D + k * D + n]
                       : W3[((l * 3) + (c - 1)) * D * D + k * D + n];
    __nv_bfloat16 hi = __float2bfloat16(v);
    float hf = __bfloat162float(hi);
    __nv_bfloat16 lo = __float2bfloat16(v - hf);
    g_Bhi[idx] = hi;
    g_Blo[idx] = lo;
}

// ---------------- warp-MMA GEMM (HMMA m16n8k16 bf16, fp32 acc) ----------------
constexpr int APITCH = 72;
constexpr int OFF_A_HI = 0;
constexpr int OFF_A_LO = 128 * APITCH * 2;
constexpr int OFF_B_HI = 2 * 128 * APITCH * 2;
constexpr int OFF_B_LO = 3 * 128 * APITCH * 2;
constexpr int SMEM_GEMM = 4 * 128 * APITCH * 2;

__device__ __forceinline__ void mma16816(float* d, const uint32_t* a, const uint32_t* b) {
    asm volatile("mma.sync.aligned.m16n8k16.row.col.f32.bf16.bf16.f32 "
        "{%0,%1,%2,%3}, {%4,%5,%6,%7}, {%8,%9}, {%0,%1,%2,%3};"
        : "+f"(d[0]), "+f"(d[1]), "+f"(d[2]), "+f"(d[3])
        : "r"(a[0]), "r"(a[1]), "r"(a[2]), "r"(a[3]), "r"(b[0]), "r"(b[1]));
}

__global__ void __launch_bounds__(256, 2)
k_gemm_mma(const float* __restrict__ x, int use_h, int layer,
           const float* __restrict__ bias, float* __restrict__ dout, int last, int N) {
    extern __shared__ char smem[];
    __nv_bfloat16* Ah = (__nv_bfloat16*)(smem + OFF_A_HI);
    __nv_bfloat16* Al = (__nv_bfloat16*)(smem + OFF_A_LO);
    __nv_bfloat16* Bh = (__nv_bfloat16*)(smem + OFF_B_HI);
    __nv_bfloat16* Bl = (__nv_bfloat16*)(smem + OFF_B_LO);

    int tid = threadIdx.x;
    int wid = tid >> 5;
    int lane = tid & 31;
    int group = lane >> 2;
    int tg = lane & 3;
    int warp_m = wid >> 2;
    int warp_n = wid & 3;
    int bm0 = blockIdx.x * 128;

    const float* Ap0 = use_h ? g_h : x;
    const float* Ap[4] = { Ap0, g_agg, g_agg + (size_t)N * D, g_agg + 2 * (size_t)N * D };
    const __nv_bfloat16* BhiL = g_Bhi + (size_t)layer * 4 * D * D;
    const __nv_bfloat16* BloL = g_Blo + (size_t)layer * 4 * D * D;

    float acc[4][4][4];
    #pragma unroll
    for (int mt = 0; mt < 4; mt++)
        #pragma unroll
        for (int nt = 0; nt < 4; nt++)
            #pragma unroll
            for (int j = 0; j < 4; j++) acc[mt][nt][j] = 0.f;

    for (int chunk = 0; chunk < 8; chunk++) {
        int c = chunk >> 1;
        int koff = (chunk & 1) * 64;
        const float* __restrict__ A = Ap[c];

        #pragma unroll
        for (int i = 0; i < 8; i++) {
            int idx = tid + i * 256;
            int row = idx >> 4;
            int q = idx & 15;
            int gr = bm0 + row;
            float4 v = make_float4(0.f, 0.f, 0.f, 0.f);
            if (gr < N) v = *(const float4*)(A + (size_t)gr * D + koff + q * 4);
            __nv_bfloat16 h0 = __float2bfloat16(v.x);
            __nv_bfloat16 h1 = __float2bfloat16(v.y);
            __nv_bfloat16 h2 = __float2bfloat16(v.z);
            __nv_bfloat16 h3 = __float2bfloat16(v.w);
            __nv_bfloat16 l0 = __float2bfloat16(v.x - __bfloat162float(h0));
            __nv_bfloat16 l1 = __float2bfloat16(v.y - __bfloat162float(h1));
            __nv_bfloat16 l2 = __float2bfloat16(v.z - __bfloat162float(h2));
            __nv_bfloat16 l3 = __float2bfloat16(v.w - __bfloat162float(h3));
            uint32_t hp0 = ((uint32_t)__bfloat16_as_ushort(h1) << 16) | __bfloat16_as_ushort(h0);
            uint32_t hp1 = ((uint32_t)__bfloat16_as_ushort(h3) << 16) | __bfloat16_as_ushort(h2);
            uint32_t lp0 = ((uint32_t)__bfloat16_as_ushort(l1) << 16) | __bfloat16_as_ushort(l0);
            uint32_t lp1 = ((uint32_t)__bfloat16_as_ushort(l3) << 16) | __bfloat16_as_ushort(l2);
            int so = row * APITCH + q * 4;
            *(uint2*)(Ah + so) = make_uint2(hp0, hp1);
            *(uint2*)(Al + so) = make_uint2(lp0, lp1);
        }
        const __nv_bfloat16* bh = BhiL + c * D * D + koff;
        const __nv_bfloat16* bl = BloL + c * D * D + koff;
        #pragma unroll
        for (int i = 0; i < 4; i++) {
            int idx = tid + i * 256;
            int row = idx >> 3;
            int q = idx & 7;
            int so = row * APITCH + q * 8;
            *(uint4*)(Bh + so) = *(const uint4*)(bh + row * D + q * 8);
            *(uint4*)(Bl + so) = *(const uint4*)(bl + row * D + q * 8);
        }
        __syncthreads();

        #pragma unroll
        for (int s = 0; s < 4; s++) {
            int ks = s * 16;
            uint32_t bhf[4][2], blf[4][2];
            #pragma unroll
            for (int nt = 0; nt < 4; nt++) {
                int n0 = warp_n * 32 + nt * 8 + group;
                int o = n0 * APITCH + ks + tg * 2;
                bhf[nt][0] = *(const uint32_t*)(Bh + o);
                bhf[nt][1] = *(const uint32_t*)(Bh + o + 8);
                blf[nt][0] = *(const uint32_t*)(Bl + o);
                blf[nt][1] = *(const uint32_t*)(Bl + o + 8);
            }
            #pragma unroll
            for (int mt = 0; mt < 4; mt++) {
                int r0 = warp_m * 64 + mt * 16 + group;
                int o = r0 * APITCH + ks + tg * 2;
                uint32_t ahf[4], alf[4];
                ahf[0] = *(const uint32_t*)(Ah + o);
                ahf[1] = *(const uint32_t*)(Ah + o + 8 * APITCH);
                ahf[2] = *(const uint32_t*)(Ah + o + 8);
                ahf[3] = *(const uint32_t*)(Ah + o + 8 * APITCH + 8);
                alf[0] = *(const uint32_t*)(Al + o);
                alf[1] = *(const uint32_t*)(Al + o + 8 * APITCH);
                alf[2] = *(const uint32_t*)(Al + o + 8);
                alf[3] = *(const uint32_t*)(Al + o + 8 * APITCH + 8);
                #pragma unroll
                for (int nt = 0; nt < 4; nt++) {
                    mma16816(acc[mt][nt], ahf, bhf[nt]);
                    mma16816(acc[mt][nt], ahf, blf[nt]);
                    mma16816(acc[mt][nt], alf, bhf[nt]);
                }
            }
        }
        __syncthreads();
    }

    float* outbuf = last ? dout : g_h;
    #pragma unroll
    for (int mt = 0; mt < 4; mt++) {
        int r0 = bm0 + warp_m * 64 + mt * 16 + group;
        #pragma unroll
        for (int nt = 0; nt < 4; nt++) {
            int c0 = warp_n * 32 + nt * 8 + tg * 2;
            float b0 = bias[c0], b1 = bias[c0 + 1];
            if (r0 < N) {
                float2 o = make_float2(acc[mt][nt][0] + b0, acc[mt][nt][1] + b1);
                *(float2*)(outbuf + (size_t)r0 * D + c0) = o;
            }
            if (r0 + 8 < N) {
                float2 o = make_float2(acc[mt][nt][2] + b0, acc[mt][nt][3] + b1);
                *(float2*)(outbuf + (size_t)(r0 + 8) * D + c0) = o;
            }
        }
    }
}

// ---------------- LayerNorm + ReLU over g_h (warp per row) ----------------
__global__ void k_lnrelu(const float* __restrict__ lng, const float* __restrict__ lnb, int N) {
    int wid = threadIdx.x >> 5;
    int lane = threadIdx.x & 31;
    int row = blockIdx.x * 8 + wid;
    if (row >= N) return;
    float4 v = *(float4*)(g_h + (size_t)row * D + lane * 4);
    float s = v.x + v.y + v.z + v.w;
    float sq = v.x * v.x + v.y * v.y + v.z * v.z + v.w * v.w;
    #pragma unroll
    for (int o = 16; o > 0; o >>= 1) {
        s  += __shfl_xor_sync(0xffffffffu, s, o);
        sq += __shfl_xor_sync(0xffffffffu, sq, o);
    }
    float mu = s * (1.0f / 128.0f);
    float var = sq * (1.0f / 128.0f) - mu * mu;
    float rs = rsqrtf(var + 1e-5f);
    float4 g = *(const float4*)(lng + lane * 4);
    float4 b = *(const float4*)(lnb + lane * 4);
    float4 o;
    o.x = fmaxf((v.x - mu) * rs * g.x + b.x, 0.f);
    o.y = fmaxf((v.y - mu) * rs * g.y + b.y, 0.f);
    o.z = fmaxf((v.z - mu) * rs * g.z + b.z, 0.f);
    o.w = fmaxf((v.w - mu) * rs * g.w + b.w, 0.f);
    *(float4*)(g_h + (size_t)row * D + lane * 4) = o;
}

// ---------------- launch ----------------
extern "C" void kernel_launch(void* const* d_in, const int* in_sizes, int n_in,
                              void* d_out, int out_size) {
    const float* x    = (const float*)d_in[0];
    const int*   ei   = (const int*)d_in[1];
    const float* asp  = (const float*)d_in[2];
    const float* actx = (const float*)d_in[3];
    const float* alat = (const float*)d_in[4];
    const float* wsp  = (const float*)d_in[5];
    const float* wctx = (const float*)d_in[6];
    const float* wlat = (const float*)d_in[7];
    const float* W3   = (const float*)d_in[8];   // [L,3,D,D]
    const float* Wslf = (const float*)d_in[9];   // [L,D,D]
    const float* bias = (const float*)d_in[10];  // [L,D]
    const float* degp = (const float*)d_in[11];  // [L,3]
    const float* lng  = (const float*)d_in[12];
    const float* lnb  = (const float*)d_in[13];
    float* out = (float*)d_out;

    int N = in_sizes[0] / D;
    int E = in_sizes[2];
    int L = in_sizes[10] / D;
    int nblk = (N + 255) / 256;

    cudaFuncSetAttribute(k_gemm_mma, cudaFuncAttributeMaxDynamicSharedMemorySize, SMEM_GEMM);

    k_init<<<(N + 255) / 256, 256>>>(N);
    k_edge1<<<(E + 255) / 256, 256>>>(ei, N, E);
    k_scan1<<<nblk, 256>>>(N);
    k_scan2<<<1, 256>>>(nblk, E, N);
    k_scan3<<<nblk, 256>>>(N);
    k_edge2<<<(E + 255) / 256, 256>>>(ei, asp, actx, alat, wsp, wctx, wlat, N, E);
    k_deg<<<(N * 32 + 255) / 256, 256>>>(N);
    k_prepB<<<(L * 4 * D * D + 255) / 256, 256>>>(Wslf, W3, L);

    int gemm_grid = (N + 127) / 128;
    for (int l = 0; l < L; l++) {
        int use_h = (l > 0) ? 1 : 0;
        int last = (l == L - 1) ? 1 : 0;
        k_dinv4<<<(N + 255) / 256, 256>>>(degp, l, N);
        k_agg<<<(N * 32 + 255) / 256, 256>>>(x, use_h, N);
        k_gemm_mma<<<gemm_grid, 256, SMEM_GEMM>>>(x, use_h, l, bias + l * D, out, last, N);
        if (!last) k_lnrelu<<<(N + 7) / 8, 256>>>(lng, lnb, N);
    }
}

// round 7
// speedup vs baseline: 3.4378x; 1.1828x over previous
#include <cuda_runtime.h>
#include <cuda_bf16.h>
#include <cstdint>

#define D 128
constexpr int MAXN = 50048;          // 391 * 128 exactly
constexpr int MAXE = 1000192;

// ---------------- scratch (static device globals; no allocation) ----------------
__device__ float  g_deg  [3 * MAXN];
__device__ float4 g_dinv4[MAXN];          // (d0, d1, d2, -) per node, current layer
__device__ int    g_count[MAXN];
__device__ int    g_rowstart[MAXN + 1];
__device__ int    g_cursor[MAXN];
__device__ float4 g_eff4 [MAXE];          // (e0, e1, e2, sid-as-int-bits) at CSR position
__device__ float  g_h    [MAXN * D];      // inter-layer activations (fp32, for gather)
__device__ int    g_blksum[256];
__device__ int    g_blkoff[256];
// split-bf16 activations for GEMM A: [c][MAXN][D], c=0 self, c=1..3 agg channels
__device__ __nv_bfloat16 g_acth[4 * MAXN * D];
__device__ __nv_bfloat16 g_actl[4 * MAXN * D];
// split-bf16 weights, transposed to [l][c][n][k] (B as N x K, K-major)
__device__ __nv_bfloat16 g_Bhi[2 * 4 * D * D];
__device__ __nv_bfloat16 g_Blo[2 * 4 * D * D];

__device__ __forceinline__ void split_bf16(float v, __nv_bfloat16& hi, __nv_bfloat16& lo) {
    hi = __float2bfloat16(v);
    lo = __float2bfloat16(v - __bfloat162float(hi));
}
__device__ __forceinline__ uint32_t pack2(__nv_bfloat16 a, __nv_bfloat16 b) {
    return ((uint32_t)__bfloat16_as_ushort(b) << 16) | __bfloat16_as_ushort(a);
}

// ---------------- init: count = 0 ----------------
__global__ void k_init(int N) {
    int i = blockIdx.x * blockDim.x + threadIdx.x;
    if (i < N) g_count[i] = 0;
}

// ---------------- edge pass 1: target histogram only (1 int atomic/edge) ----------------
__global__ void k_edge1(const int* __restrict__ ei, int N, int E) {
    int e = blockIdx.x * blockDim.x + threadIdx.x;
    if (e >= E) return;
    atomicAdd(&g_count[ei[E + e]], 1);
}

// ---------------- block scans ----------------
__device__ __forceinline__ int block_incl_scan(int v, int* s) {
    int tid = threadIdx.x;
    s[tid] = v;
    __syncthreads();
    #pragma unroll
    for (int o = 1; o < 256; o <<= 1) {
        int t = (tid >= o) ? s[tid - o] : 0;
        __syncthreads();
        s[tid] += t;
        __syncthreads();
    }
    return s[tid];
}

__global__ void k_scan1(int N) {
    __shared__ int s[256];
    int i = blockIdx.x * 256 + threadIdx.x;
    int v = (i < N) ? g_count[i] : 0;
    block_incl_scan(v, s);
    if (threadIdx.x == 255) g_blksum[blockIdx.x] = s[255];
}

__global__ void k_scan2(int nblk, int E, int N) {
    __shared__ int s[256];
    int tid = threadIdx.x;
    int v = (tid < nblk) ? g_blksum[tid] : 0;
    int inc = block_incl_scan(v, s);
    g_blkoff[tid] = inc - v;
    if (tid == 0) g_rowstart[N] = E;
}

__global__ void k_scan3(int N) {
    __shared__ int s[256];
    int i = blockIdx.x * 256 + threadIdx.x;
    int v = (i < N) ? g_count[i] : 0;
    int inc = block_incl_scan(v, s);
    if (i < N) {
        int excl = inc - v + g_blkoff[blockIdx.x];
        g_rowstart[i] = excl;
        g_cursor[i] = excl;
    }
}

// ---------------- edge pass 2: scatter (eff0,eff1,eff2,sid) into CSR slots ----------------
__global__ void k_edge2(const int* __restrict__ ei,
                        const float* __restrict__ asp, const float* __restrict__ actx,
                        const float* __restrict__ alat,
                        const float* __restrict__ wsp, const float* __restrict__ wctx,
                        const float* __restrict__ wlat, int N, int E) {
    int e = blockIdx.x * blockDim.x + threadIdx.x;
    if (e >= E) return;
    int t = ei[E + e];
    int s = ei[e];
    int p = atomicAdd(&g_cursor[t], 1);
    float4 v;
    v.x = asp[e]  * wsp[e];
    v.y = actx[e] * wctx[e];
    v.z = alat[e] * wlat[e];
    v.w = __int_as_float(s);
    g_eff4[p] = v;
}

// ---------------- degrees from CSR rows (no float atomics); warp per node ----------------
__global__ void k_deg(int N) {
    int gw = (blockIdx.x * blockDim.x + threadIdx.x) >> 5;
    int lane = threadIdx.x & 31;
    if (gw >= N) return;
    int s = g_rowstart[gw], e = g_rowstart[gw + 1];
    float d0 = 0.f, d1 = 0.f, d2 = 0.f;
    for (int p = s + lane; p < e; p += 32) {
        float4 v = __ldg(&g_eff4[p]);
        d0 += v.x; d1 += v.y; d2 += v.z;
    }
    #pragma unroll
    for (int o = 16; o > 0; o >>= 1) {
        d0 += __shfl_xor_sync(0xffffffffu, d0, o);
        d1 += __shfl_xor_sync(0xffffffffu, d1, o);
        d2 += __shfl_xor_sync(0xffffffffu, d2, o);
    }
    if (lane == 0) {
        g_deg[gw]         = 1.f + d0;
        g_deg[N + gw]     = 1.f + d1;
        g_deg[2 * N + gw] = 1.f + d2;
    }
}

// ---------------- per-layer: dinv4[n] = clip(deg,1e-6)^p for 3 channels ----------------
__global__ void k_dinv4(const float* __restrict__ deg_power, int l, int N) {
    int i = blockIdx.x * blockDim.x + threadIdx.x;
    if (i >= N) return;
    float p0 = deg_power[l * 3 + 0];
    float p1 = deg_power[l * 3 + 1];
    float p2 = deg_power[l * 3 + 2];
    float4 o;
    o.x = powf(fmaxf(g_deg[i],         1e-6f), p0);
    o.y = powf(fmaxf(g_deg[N + i],     1e-6f), p1);
    o.z = powf(fmaxf(g_deg[2 * N + i], 1e-6f), p2);
    o.w = 0.f;
    g_dinv4[i] = o;
}

// ---------------- prepX: split x into channel 0 of act buffers ----------------
__global__ void k_prepX(const float* __restrict__ x, int N) {
    int i = blockIdx.x * blockDim.x + threadIdx.x;   // one float4 each
    if (i >= N * (D / 4)) return;
    float4 v = __ldg((const float4*)x + i);
    __nv_bfloat16 h0, h1, h2, h3, l0, l1, l2, l3;
    split_bf16(v.x, h0, l0); split_bf16(v.y, h1, l1);
    split_bf16(v.z, h2, l2); split_bf16(v.w, h3, l3);
    *(uint2*)(g_acth + (size_t)i * 4) = make_uint2(pack2(h0, h1), pack2(h2, h3));
    *(uint2*)(g_actl + (size_t)i * 4) = make_uint2(pack2(l0, l1), pack2(l2, l3));
}

// ---------------- aggregate: ONE WARP per target node; lane owns 4 features ----------------
// writes split bf16 directly into act channels 1..3
__global__ void __launch_bounds__(256)
k_agg(const float* __restrict__ x, int use_h, int N) {
    int gw = (blockIdx.x * blockDim.x + threadIdx.x) >> 5;
    int lane = threadIdx.x & 31;
    if (gw >= N) return;
    const float* __restrict__ X = use_h ? g_h : x;
    int s = g_rowstart[gw];
    int e = g_rowstart[gw + 1];
    int fo = lane * 4;

    float4 a0 = make_float4(0.f, 0.f, 0.f, 0.f);
    float4 a1 = make_float4(0.f, 0.f, 0.f, 0.f);
    float4 a2 = make_float4(0.f, 0.f, 0.f, 0.f);

    int p = s;
    for (; p + 4 <= e; p += 4) {
        float4 e0 = __ldg(&g_eff4[p]);
        float4 e1 = __ldg(&g_eff4[p + 1]);
        float4 e2 = __ldg(&g_eff4[p + 2]);
        float4 e3 = __ldg(&g_eff4[p + 3]);
        int s0 = __float_as_int(e0.w);
        int s1 = __float_as_int(e1.w);
        int s2 = __float_as_int(e2.w);
        int s3 = __float_as_int(e3.w);
        float4 d0 = __ldg(&g_dinv4[s0]);
        float4 d1 = __ldg(&g_dinv4[s1]);
        float4 d2 = __ldg(&g_dinv4[s2]);
        float4 d3 = __ldg(&g_dinv4[s3]);
        float4 x0 = __ldg((const float4*)(X + (size_t)s0 * D + fo));
        float4 x1 = __ldg((const float4*)(X + (size_t)s1 * D + fo));
        float4 x2 = __ldg((const float4*)(X + (size_t)s2 * D + fo));
        float4 x3 = __ldg((const float4*)(X + (size_t)s3 * D + fo));
        float m;
        m = e0.x * d0.x; a0.x = fmaf(m, x0.x, a0.x); a0.y = fmaf(m, x0.y, a0.y); a0.z = fmaf(m, x0.z, a0.z); a0.w = fmaf(m, x0.w, a0.w);
        m = e0.y * d0.y; a1.x = fmaf(m, x0.x, a1.x); a1.y = fmaf(m, x0.y, a1.y); a1.z = fmaf(m, x0.z, a1.z); a1.w = fmaf(m, x0.w, a1.w);
        m = e0.z * d0.z; a2.x = fmaf(m, x0.x, a2.x); a2.y = fmaf(m, x0.y, a2.y); a2.z = fmaf(m, x0.z, a2.z); a2.w = fmaf(m, x0.w, a2.w);
        m = e1.x * d1.x; a0.x = fmaf(m, x1.x, a0.x); a0.y = fmaf(m, x1.y, a0.y); a0.z = fmaf(m, x1.z, a0.z); a0.w = fmaf(m, x1.w, a0.w);
        m = e1.y * d1.y; a1.x = fmaf(m, x1.x, a1.x); a1.y = fmaf(m, x1.y, a1.y); a1.z = fmaf(m, x1.z, a1.z); a1.w = fmaf(m, x1.w, a1.w);
        m = e1.z * d1.z; a2.x = fmaf(m, x1.x, a2.x); a2.y = fmaf(m, x1.y, a2.y); a2.z = fmaf(m, x1.z, a2.z); a2.w = fmaf(m, x1.w, a2.w);
        m = e2.x * d2.x; a0.x = fmaf(m, x2.x, a0.x); a0.y = fmaf(m, x2.y, a0.y); a0.z = fmaf(m, x2.z, a0.z); a0.w = fmaf(m, x2.w, a0.w);
        m = e2.y * d2.y; a1.x = fmaf(m, x2.x, a1.x); a1.y = fmaf(m, x2.y, a1.y); a1.z = fmaf(m, x2.z, a1.z); a1.w = fmaf(m, x2.w, a1.w);
        m = e2.z * d2.z; a2.x = fmaf(m, x2.x, a2.x); a2.y = fmaf(m, x2.y, a2.y); a2.z = fmaf(m, x2.z, a2.z); a2.w = fmaf(m, x2.w, a2.w);
        m = e3.x * d3.x; a0.x = fmaf(m, x3.x, a0.x); a0.y = fmaf(m, x3.y, a0.y); a0.z = fmaf(m, x3.z, a0.z); a0.w = fmaf(m, x3.w, a0.w);
        m = e3.y * d3.y; a1.x = fmaf(m, x3.x, a1.x); a1.y = fmaf(m, x3.y, a1.y); a1.z = fmaf(m, x3.z, a1.z); a1.w = fmaf(m, x3.w, a1.w);
        m = e3.z * d3.z; a2.x = fmaf(m, x3.x, a2.x); a2.y = fmaf(m, x3.y, a2.y); a2.z = fmaf(m, x3.z, a2.z); a2.w = fmaf(m, x3.w, a2.w);
    }
    for (; p < e; p++) {
        float4 ef = __ldg(&g_eff4[p]);
        int sid = __float_as_int(ef.w);
        float4 dv = __ldg(&g_dinv4[sid]);
        float4 xv = __ldg((const float4*)(X + (size_t)sid * D + fo));
        float m0 = ef.x * dv.x, m1 = ef.y * dv.y, m2 = ef.z * dv.z;
        a0.x = fmaf(m0, xv.x, a0.x); a0.y = fmaf(m0, xv.y, a0.y); a0.z = fmaf(m0, xv.z, a0.z); a0.w = fmaf(m0, xv.w, a0.w);
        a1.x = fmaf(m1, xv.x, a1.x); a1.y = fmaf(m1, xv.y, a1.y); a1.z = fmaf(m1, xv.z, a1.z); a1.w = fmaf(m1, xv.w, a1.w);
        a2.x = fmaf(m2, xv.x, a2.x); a2.y = fmaf(m2, xv.y, a2.y); a2.z = fmaf(m2, xv.z, a2.z); a2.w = fmaf(m2, xv.w, a2.w);
    }

    float4 dt = g_dinv4[gw];
    a0.x *= dt.x; a0.y *= dt.x; a0.z *= dt.x; a0.w *= dt.x;
    a1.x *= dt.y; a1.y *= dt.y; a1.z *= dt.y; a1.w *= dt.y;
    a2.x *= dt.z; a2.y *= dt.z; a2.z *= dt.z; a2.w *= dt.z;

    // split & store to channels 1..3
    float4 vals[3] = { a0, a1, a2 };
    #pragma unroll
    for (int c = 0; c < 3; c++) {
        float4 v = vals[c];
        __nv_bfloat16 h0, h1, h2, h3, l0, l1, l2, l3;
        split_bf16(v.x, h0, l0); split_bf16(v.y, h1, l1);
        split_bf16(v.z, h2, l2); split_bf16(v.w, h3, l3);
        size_t off = ((size_t)(c + 1) * MAXN + gw) * D + fo;
        *(uint2*)(g_acth + off) = make_uint2(pack2(h0, h1), pack2(h2, h3));
        *(uint2*)(g_actl + off) = make_uint2(pack2(l0, l1), pack2(l2, l3));
    }
}

// ---------------- prepB: split weights to bf16 hi/lo, transposed [l][c][n][k] ----------------
__global__ void k_prepB(const float* __restrict__ Wself, const float* __restrict__ W3, int L) {
    int idx = blockIdx.x * blockDim.x + threadIdx.x;
    int total = L * 4 * D * D;
    if (idx >= total) return;
    int l  = idx / (4 * D * D);
    int r  = idx % (4 * D * D);
    int c  = r / (D * D);
    int nk = r % (D * D);
    int n  = nk >> 7;
    int k  = nk & 127;
    float v = (c == 0) ? Wself[l * D * D + k * D + n]
                       : W3[((l * 3) + (c - 1)) * D * D + k * D + n];
    __nv_bfloat16 hi, lo;
    split_bf16(v, hi, lo);
    g_Bhi[idx] = hi;
    g_Blo[idx] = lo;
}

// ---------------- warp-MMA GEMM (HMMA m16n8k16 bf16, fp32 acc) ----------------
// A operands pre-split in g_acth/g_actl -> staging is pure uint4 copies.
constexpr int APITCH = 72;
constexpr int OFF_A_HI = 0;
constexpr int OFF_A_LO = 128 * APITCH * 2;
constexpr int OFF_B_HI = 2 * 128 * APITCH * 2;
constexpr int OFF_B_LO = 3 * 128 * APITCH * 2;
constexpr int SMEM_GEMM = 4 * 128 * APITCH * 2;

__device__ __forceinline__ void mma16816(float* d, const uint32_t* a, const uint32_t* b) {
    asm volatile("mma.sync.aligned.m16n8k16.row.col.f32.bf16.bf16.f32 "
        "{%0,%1,%2,%3}, {%4,%5,%6,%7}, {%8,%9}, {%0,%1,%2,%3};"
        : "+f"(d[0]), "+f"(d[1]), "+f"(d[2]), "+f"(d[3])
        : "r"(a[0]), "r"(a[1]), "r"(a[2]), "r"(a[3]), "r"(b[0]), "r"(b[1]));
}

__global__ void __launch_bounds__(256, 2)
k_gemm_mma(int layer, const float* __restrict__ bias,
           float* __restrict__ dout, int last, int N) {
    extern __shared__ char smem[];
    __nv_bfloat16* Ah = (__nv_bfloat16*)(smem + OFF_A_HI);
    __nv_bfloat16* Al = (__nv_bfloat16*)(smem + OFF_A_LO);
    __nv_bfloat16* Bh = (__nv_bfloat16*)(smem + OFF_B_HI);
    __nv_bfloat16* Bl = (__nv_bfloat16*)(smem + OFF_B_LO);

    int tid = threadIdx.x;
    int wid = tid >> 5;
    int lane = tid & 31;
    int group = lane >> 2;
    int tg = lane & 3;
    int warp_m = wid >> 2;
    int warp_n = wid & 3;
    int bm0 = blockIdx.x * 128;

    const __nv_bfloat16* BhiL = g_Bhi + (size_t)layer * 4 * D * D;
    const __nv_bfloat16* BloL = g_Blo + (size_t)layer * 4 * D * D;

    float acc[4][4][4];
    #pragma unroll
    for (int mt = 0; mt < 4; mt++)
        #pragma unroll
        for (int nt = 0; nt < 4; nt++)
            #pragma unroll
            for (int j = 0; j < 4; j++) acc[mt][nt][j] = 0.f;

    for (int chunk = 0; chunk < 8; chunk++) {
        int c = chunk >> 1;
        int koff = (chunk & 1) * 64;

        // ---- stage A: pure copies (rows >= N are zero in the act buffers) ----
        const __nv_bfloat16* ah = g_acth + ((size_t)c * MAXN + bm0) * D + koff;
        const __nv_bfloat16* al = g_actl + ((size_t)c * MAXN + bm0) * D + koff;
        #pragma unroll
        for (int i = 0; i < 4; i++) {
            int idx = tid + i * 256;          // < 1024
            int row = idx >> 3;
            int q = idx & 7;                  // 8 bf16 each
            int so = row * APITCH + q * 8;
            size_t go = (size_t)row * D + q * 8;
            *(uint4*)(Ah + so) = *(const uint4*)(ah + go);
            *(uint4*)(Al + so) = *(const uint4*)(al + go);
        }
        // ---- stage B: pure copies ----
        const __nv_bfloat16* bh = BhiL + c * D * D + koff;
        const __nv_bfloat16* bl = BloL + c * D * D + koff;
        #pragma unroll
        for (int i = 0; i < 4; i++) {
            int idx = tid + i * 256;
            int row = idx >> 3;
            int q = idx & 7;
            int so = row * APITCH + q * 8;
            *(uint4*)(Bh + so) = *(const uint4*)(bh + row * D + q * 8);
            *(uint4*)(Bl + so) = *(const uint4*)(bl + row * D + q * 8);
        }
        __syncthreads();

        #pragma unroll
        for (int s = 0; s < 4; s++) {
            int ks = s * 16;
            uint32_t bhf[4][2], blf[4][2];
            #pragma unroll
            for (int nt = 0; nt < 4; nt++) {
                int n0 = warp_n * 32 + nt * 8 + group;
                int o = n0 * APITCH + ks + tg * 2;
                bhf[nt][0] = *(const uint32_t*)(Bh + o);
                bhf[nt][1] = *(const uint32_t*)(Bh + o + 8);
                blf[nt][0] = *(const uint32_t*)(Bl + o);
                blf[nt][1] = *(const uint32_t*)(Bl + o + 8);
            }
            #pragma unroll
            for (int mt = 0; mt < 4; mt++) {
                int r0 = warp_m * 64 + mt * 16 + group;
                int o = r0 * APITCH + ks + tg * 2;
                uint32_t ahf[4], alf[4];
                ahf[0] = *(const uint32_t*)(Ah + o);
                ahf[1] = *(const uint32_t*)(Ah + o + 8 * APITCH);
                ahf[2] = *(const uint32_t*)(Ah + o + 8);
                ahf[3] = *(const uint32_t*)(Ah + o + 8 * APITCH + 8);
                alf[0] = *(const uint32_t*)(Al + o);
                alf[1] = *(const uint32_t*)(Al + o + 8 * APITCH);
                alf[2] = *(const uint32_t*)(Al + o + 8);
                alf[3] = *(const uint32_t*)(Al + o + 8 * APITCH + 8);
                #pragma unroll
                for (int nt = 0; nt < 4; nt++) {
                    mma16816(acc[mt][nt], ahf, bhf[nt]);
                    mma16816(acc[mt][nt], ahf, blf[nt]);
                    mma16816(acc[mt][nt], alf, bhf[nt]);
                }
            }
        }
        __syncthreads();
    }

    float* outbuf = last ? dout : g_h;
    #pragma unroll
    for (int mt = 0; mt < 4; mt++) {
        int r0 = bm0 + warp_m * 64 + mt * 16 + group;
        #pragma unroll
        for (int nt = 0; nt < 4; nt++) {
            int c0 = warp_n * 32 + nt * 8 + tg * 2;
            float b0 = bias[c0], b1 = bias[c0 + 1];
            if (r0 < N) {
                float2 o = make_float2(acc[mt][nt][0] + b0, acc[mt][nt][1] + b1);
                *(float2*)(outbuf + (size_t)r0 * D + c0) = o;
            }
            if (r0 + 8 < N) {
                float2 o = make_float2(acc[mt][nt][2] + b0, acc[mt][nt][3] + b1);
                *(float2*)(outbuf + (size_t)(r0 + 8) * D + c0) = o;
            }
        }
    }
}

// ---------------- LayerNorm + ReLU over g_h; also writes split channel 0 ----------------
__global__ void k_lnrelu(const float* __restrict__ lng, const float* __restrict__ lnb, int N) {
    int wid = threadIdx.x >> 5;
    int lane = threadIdx.x & 31;
    int row = blockIdx.x * 8 + wid;
    if (row >= N) return;
    float4 v = *(float4*)(g_h + (size_t)row * D + lane * 4);
    float s = v.x + v.y + v.z + v.w;
    float sq = v.x * v.x + v.y * v.y + v.z * v.z + v.w * v.w;
    #pragma unroll
    for (int o = 16; o > 0; o >>= 1) {
        s  += __shfl_xor_sync(0xffffffffu, s, o);
        sq += __shfl_xor_sync(0xffffffffu, sq, o);
    }
    float mu = s * (1.0f / 128.0f);
    float var = sq * (1.0f / 128.0f) - mu * mu;
    float rs = rsqrtf(var + 1e-5f);
    float4 g = *(const float4*)(lng + lane * 4);
    float4 b = *(const float4*)(lnb + lane * 4);
    float4 o;
    o.x = fmaxf((v.x - mu) * rs * g.x + b.x, 0.f);
    o.y = fmaxf((v.y - mu) * rs * g.y + b.y, 0.f);
    o.z = fmaxf((v.z - mu) * rs * g.z + b.z, 0.f);
    o.w = fmaxf((v.w - mu) * rs * g.w + b.w, 0.f);
    *(float4*)(g_h + (size_t)row * D + lane * 4) = o;

    __nv_bfloat16 h0, h1, h2, h3, l0, l1, l2, l3;
    split_bf16(o.x, h0, l0); split_bf16(o.y, h1, l1);
    split_bf16(o.z, h2, l2); split_bf16(o.w, h3, l3);
    size_t off = (size_t)row * D + lane * 4;
    *(uint2*)(g_acth + off) = make_uint2(pack2(h0, h1), pack2(h2, h3));
    *(uint2*)(g_actl + off) = make_uint2(pack2(l0, l1), pack2(l2, l3));
}

// ---------------- launch ----------------
extern "C" void kernel_launch(void* const* d_in, const int* in_sizes, int n_in,
                              void* d_out, int out_size) {
    const float* x    = (const float*)d_in[0];
    const int*   ei   = (const int*)d_in[1];
    const float* asp  = (const float*)d_in[2];
    const float* actx = (const float*)d_in[3];
    const float* alat = (const float*)d_in[4];
    const float* wsp  = (const float*)d_in[5];
    const float* wctx = (const float*)d_in[6];
    const float* wlat = (const float*)d_in[7];
    const float* W3   = (const float*)d_in[8];   // [L,3,D,D]
    const float* Wslf = (const float*)d_in[9];   // [L,D,D]
    const float* bias = (const float*)d_in[10];  // [L,D]
    const float* degp = (const float*)d_in[11];  // [L,3]
    const float* lng  = (const float*)d_in[12];
    const float* lnb  = (const float*)d_in[13];
    float* out = (float*)d_out;

    int N = in_sizes[0] / D;
    int E = in_sizes[2];
    int L = in_sizes[10] / D;
    int nblk = (N + 255) / 256;

    cudaFuncSetAttribute(k_gemm_mma, cudaFuncAttributeMaxDynamicSharedMemorySize, SMEM_GEMM);

    k_init<<<(N + 255) / 256, 256>>>(N);
    k_edge1<<<(E + 255) / 256, 256>>>(ei, N, E);
    k_scan1<<<nblk, 256>>>(N);
    k_scan2<<<1, 256>>>(nblk, E, N);
    k_scan3<<<nblk, 256>>>(N);
    k_edge2<<<(E + 255) / 256, 256>>>(ei, asp, actx, alat, wsp, wctx, wlat, N, E);
    k_deg<<<(N * 32 + 255) / 256, 256>>>(N);
    k_prepB<<<(L * 4 * D * D + 255) / 256, 256>>>(Wslf, W3, L);
    k_prepX<<<(N * (D / 4) + 255) / 256, 256>>>(x, N);

    int gemm_grid = (N + 127) / 128;
    for (int l = 0; l < L; l++) {
        int use_h = (l > 0) ? 1 : 0;
        int last = (l == L - 1) ? 1 : 0;
        k_dinv4<<<(N + 255) / 256, 256>>>(degp, l, N);
        k_agg<<<(N * 32 + 255) / 256, 256>>>(x, use_h, N);
        k_gemm_mma<<<gemm_grid, 256, SMEM_GEMM>>>(l, bias + l * D, out, last, N);
        if (!last) k_lnrelu<<<(N + 7) / 8, 256>>>(lng, lnb, N);
    }
}

// round 8
// speedup vs baseline: 3.5560x; 1.0344x over previous
#include <cuda_runtime.h>
#include <cuda_bf16.h>
#include <cstdint>

#define D 128
constexpr int MAXN = 50048;          // 391 * 128 exactly
constexpr int MAXE = 1000192;

// ---------------- scratch (static device globals; no allocation) ----------------
__device__ float  g_deg  [3 * MAXN];
__device__ float4 g_dinv4[2 * MAXN];      // per layer: (d0, d1, d2, -) per node
__device__ int    g_count[MAXN];
__device__ int    g_rowstart[MAXN + 1];
__device__ int    g_cursor[MAXN];
__device__ float4 g_eff4 [MAXE];          // (e0, e1, e2, sid-as-int-bits) at CSR position
__device__ float  g_h    [MAXN * D];      // inter-layer activations (fp32, for gather)
__device__ int    g_blksum[256];
__device__ int    g_blkoff[256];
// split-bf16 activations for GEMM A: [c][MAXN][D], c=0 self, c=1..3 agg channels
__device__ __nv_bfloat16 g_acth[4 * MAXN * D];
__device__ __nv_bfloat16 g_actl[4 * MAXN * D];
// split-bf16 weights, transposed to [l][c][n][k] (B as N x K, K-major)
__device__ __nv_bfloat16 g_Bhi[2 * 4 * D * D];
__device__ __nv_bfloat16 g_Blo[2 * 4 * D * D];

__device__ __forceinline__ void split_bf16(float v, __nv_bfloat16& hi, __nv_bfloat16& lo) {
    hi = __float2bfloat16(v);
    lo = __float2bfloat16(v - __bfloat162float(hi));
}
__device__ __forceinline__ uint32_t pack2(__nv_bfloat16 a, __nv_bfloat16 b) {
    return ((uint32_t)__bfloat16_as_ushort(b) << 16) | __bfloat16_as_ushort(a);
}

// ---------------- init: count = 0 ----------------
__global__ void k_init(int N) {
    int i = blockIdx.x * blockDim.x + threadIdx.x;
    if (i < N) g_count[i] = 0;
}

// ---------------- edge pass 1: target histogram only (1 int atomic/edge) ----------------
__global__ void k_edge1(const int* __restrict__ ei, int N, int E) {
    int e = blockIdx.x * blockDim.x + threadIdx.x;
    if (e >= E) return;
    atomicAdd(&g_count[ei[E + e]], 1);
}

// ---------------- block scans ----------------
__device__ __forceinline__ int block_incl_scan(int v, int* s) {
    int tid = threadIdx.x;
    s[tid] = v;
    __syncthreads();
    #pragma unroll
    for (int o = 1; o < 256; o <<= 1) {
        int t = (tid >= o) ? s[tid - o] : 0;
        __syncthreads();
        s[tid] += t;
        __syncthreads();
    }
    return s[tid];
}

__global__ void k_scan1(int N) {
    __shared__ int s[256];
    int i = blockIdx.x * 256 + threadIdx.x;
    int v = (i < N) ? g_count[i] : 0;
    block_incl_scan(v, s);
    if (threadIdx.x == 255) g_blksum[blockIdx.x] = s[255];
}

__global__ void k_scan2(int nblk, int E, int N) {
    __shared__ int s[256];
    int tid = threadIdx.x;
    int v = (tid < nblk) ? g_blksum[tid] : 0;
    int inc = block_incl_scan(v, s);
    g_blkoff[tid] = inc - v;
    if (tid == 0) g_rowstart[N] = E;
}

__global__ void k_scan3(int N) {
    __shared__ int s[256];
    int i = blockIdx.x * 256 + threadIdx.x;
    int v = (i < N) ? g_count[i] : 0;
    int inc = block_incl_scan(v, s);
    if (i < N) {
        int excl = inc - v + g_blkoff[blockIdx.x];
        g_rowstart[i] = excl;
        g_cursor[i] = excl;
    }
}

// ---------------- edge pass 2: scatter (eff0,eff1,eff2,sid) into CSR slots ----------------
__global__ void k_edge2(const int* __restrict__ ei,
                        const float* __restrict__ asp, const float* __restrict__ actx,
                        const float* __restrict__ alat,
                        const float* __restrict__ wsp, const float* __restrict__ wctx,
                        const float* __restrict__ wlat, int N, int E) {
    int e = blockIdx.x * blockDim.x + threadIdx.x;
    if (e >= E) return;
    int t = ei[E + e];
    int s = ei[e];
    int p = atomicAdd(&g_cursor[t], 1);
    float4 v;
    v.x = asp[e]  * wsp[e];
    v.y = actx[e] * wctx[e];
    v.z = alat[e] * wlat[e];
    v.w = __int_as_float(s);
    g_eff4[p] = v;
}

// ---------------- degrees from CSR rows (no float atomics); warp per node ----------------
__global__ void k_deg(int N) {
    int gw = (blockIdx.x * blockDim.x + threadIdx.x) >> 5;
    int lane = threadIdx.x & 31;
    if (gw >= N) return;
    int s = g_rowstart[gw], e = g_rowstart[gw + 1];
    float d0 = 0.f, d1 = 0.f, d2 = 0.f;
    for (int p = s + lane; p < e; p += 32) {
        float4 v = __ldg(&g_eff4[p]);
        d0 += v.x; d1 += v.y; d2 += v.z;
    }
    #pragma unroll
    for (int o = 16; o > 0; o >>= 1) {
        d0 += __shfl_xor_sync(0xffffffffu, d0, o);
        d1 += __shfl_xor_sync(0xffffffffu, d1, o);
        d2 += __shfl_xor_sync(0xffffffffu, d2, o);
    }
    if (lane == 0) {
        g_deg[gw]         = 1.f + d0;
        g_deg[N + gw]     = 1.f + d1;
        g_deg[2 * N + gw] = 1.f + d2;
    }
}

// ---------------- dinv4 for ALL layers upfront ----------------
__global__ void k_dinv4(const float* __restrict__ deg_power, int L, int N) {
    int idx = blockIdx.x * blockDim.x + threadIdx.x;
    if (idx >= L * N) return;
    int l = idx / N;
    int i = idx % N;
    float p0 = deg_power[l * 3 + 0];
    float p1 = deg_power[l * 3 + 1];
    float p2 = deg_power[l * 3 + 2];
    float4 o;
    o.x = powf(fmaxf(g_deg[i],         1e-6f), p0);
    o.y = powf(fmaxf(g_deg[N + i],     1e-6f), p1);
    o.z = powf(fmaxf(g_deg[2 * N + i], 1e-6f), p2);
    o.w = 0.f;
    g_dinv4[l * MAXN + i] = o;
}

// ---------------- prepX: split x into channel 0 of act buffers ----------------
__global__ void k_prepX(const float* __restrict__ x, int N) {
    int i = blockIdx.x * blockDim.x + threadIdx.x;   // one float4 each
    if (i >= N * (D / 4)) return;
    float4 v = __ldg((const float4*)x + i);
    __nv_bfloat16 h0, h1, h2, h3, l0, l1, l2, l3;
    split_bf16(v.x, h0, l0); split_bf16(v.y, h1, l1);
    split_bf16(v.z, h2, l2); split_bf16(v.w, h3, l3);
    *(uint2*)(g_acth + (size_t)i * 4) = make_uint2(pack2(h0, h1), pack2(h2, h3));
    *(uint2*)(g_actl + (size_t)i * 4) = make_uint2(pack2(l0, l1), pack2(l2, l3));
}

// ---------------- aggregate: ONE WARP per target node; lane owns 4 features ----------------
__global__ void __launch_bounds__(256)
k_agg(const float* __restrict__ x, int use_h, int layer, int N) {
    int gw = (blockIdx.x * blockDim.x + threadIdx.x) >> 5;
    int lane = threadIdx.x & 31;
    if (gw >= N) return;
    const float* __restrict__ X = use_h ? g_h : x;
    const float4* __restrict__ dinv = g_dinv4 + layer * MAXN;
    int s = g_rowstart[gw];
    int e = g_rowstart[gw + 1];
    int fo = lane * 4;

    float4 a0 = make_float4(0.f, 0.f, 0.f, 0.f);
    float4 a1 = make_float4(0.f, 0.f, 0.f, 0.f);
    float4 a2 = make_float4(0.f, 0.f, 0.f, 0.f);

    int p = s;
    for (; p + 4 <= e; p += 4) {
        float4 e0 = __ldg(&g_eff4[p]);
        float4 e1 = __ldg(&g_eff4[p + 1]);
        float4 e2 = __ldg(&g_eff4[p + 2]);
        float4 e3 = __ldg(&g_eff4[p + 3]);
        int s0 = __float_as_int(e0.w);
        int s1 = __float_as_int(e1.w);
        int s2 = __float_as_int(e2.w);
        int s3 = __float_as_int(e3.w);
        float4 d0 = __ldg(&dinv[s0]);
        float4 d1 = __ldg(&dinv[s1]);
        float4 d2 = __ldg(&dinv[s2]);
        float4 d3 = __ldg(&dinv[s3]);
        float4 x0 = __ldg((const float4*)(X + (size_t)s0 * D + fo));
        float4 x1 = __ldg((const float4*)(X + (size_t)s1 * D + fo));
        float4 x2 = __ldg((const float4*)(X + (size_t)s2 * D + fo));
        float4 x3 = __ldg((const float4*)(X + (size_t)s3 * D + fo));
        float m;
        m = e0.x * d0.x; a0.x = fmaf(m, x0.x, a0.x); a0.y = fmaf(m, x0.y, a0.y); a0.z = fmaf(m, x0.z, a0.z); a0.w = fmaf(m, x0.w, a0.w);
        m = e0.y * d0.y; a1.x = fmaf(m, x0.x, a1.x); a1.y = fmaf(m, x0.y, a1.y); a1.z = fmaf(m, x0.z, a1.z); a1.w = fmaf(m, x0.w, a1.w);
        m = e0.z * d0.z; a2.x = fmaf(m, x0.x, a2.x); a2.y = fmaf(m, x0.y, a2.y); a2.z = fmaf(m, x0.z, a2.z); a2.w = fmaf(m, x0.w, a2.w);
        m = e1.x * d1.x; a0.x = fmaf(m, x1.x, a0.x); a0.y = fmaf(m, x1.y, a0.y); a0.z = fmaf(m, x1.z, a0.z); a0.w = fmaf(m, x1.w, a0.w);
        m = e1.y * d1.y; a1.x = fmaf(m, x1.x, a1.x); a1.y = fmaf(m, x1.y, a1.y); a1.z = fmaf(m, x1.z, a1.z); a1.w = fmaf(m, x1.w, a1.w);
        m = e1.z * d1.z; a2.x = fmaf(m, x1.x, a2.x); a2.y = fmaf(m, x1.y, a2.y); a2.z = fmaf(m, x1.z, a2.z); a2.w = fmaf(m, x1.w, a2.w);
        m = e2.x * d2.x; a0.x = fmaf(m, x2.x, a0.x); a0.y = fmaf(m, x2.y, a0.y); a0.z = fmaf(m, x2.z, a0.z); a0.w = fmaf(m, x2.w, a0.w);
        m = e2.y * d2.y; a1.x = fmaf(m, x2.x, a1.x); a1.y = fmaf(m, x2.y, a1.y); a1.z = fmaf(m, x2.z, a1.z); a1.w = fmaf(m, x2.w, a1.w);
        m = e2.z * d2.z; a2.x = fmaf(m, x2.x, a2.x); a2.y = fmaf(m, x2.y, a2.y); a2.z = fmaf(m, x2.z, a2.z); a2.w = fmaf(m, x2.w, a2.w);
        m = e3.x * d3.x; a0.x = fmaf(m, x3.x, a0.x); a0.y = fmaf(m, x3.y, a0.y); a0.z = fmaf(m, x3.z, a0.z); a0.w = fmaf(m, x3.w, a0.w);
        m = e3.y * d3.y; a1.x = fmaf(m, x3.x, a1.x); a1.y = fmaf(m, x3.y, a1.y); a1.z = fmaf(m, x3.z, a1.z); a1.w = fmaf(m, x3.w, a1.w);
        m = e3.z * d3.z; a2.x = fmaf(m, x3.x, a2.x); a2.y = fmaf(m, x3.y, a2.y); a2.z = fmaf(m, x3.z, a2.z); a2.w = fmaf(m, x3.w, a2.w);
    }
    for (; p < e; p++) {
        float4 ef = __ldg(&g_eff4[p]);
        int sid = __float_as_int(ef.w);
        float4 dv = __ldg(&dinv[sid]);
        float4 xv = __ldg((const float4*)(X + (size_t)sid * D + fo));
        float m0 = ef.x * dv.x, m1 = ef.y * dv.y, m2 = ef.z * dv.z;
        a0.x = fmaf(m0, xv.x, a0.x); a0.y = fmaf(m0, xv.y, a0.y); a0.z = fmaf(m0, xv.z, a0.z); a0.w = fmaf(m0, xv.w, a0.w);
        a1.x = fmaf(m1, xv.x, a1.x); a1.y = fmaf(m1, xv.y, a1.y); a1.z = fmaf(m1, xv.z, a1.z); a1.w = fmaf(m1, xv.w, a1.w);
        a2.x = fmaf(m2, xv.x, a2.x); a2.y = fmaf(m2, xv.y, a2.y); a2.z = fmaf(m2, xv.z, a2.z); a2.w = fmaf(m2, xv.w, a2.w);
    }

    float4 dt = dinv[gw];
    a0.x *= dt.x; a0.y *= dt.x; a0.z *= dt.x; a0.w *= dt.x;
    a1.x *= dt.y; a1.y *= dt.y; a1.z *= dt.y; a1.w *= dt.y;
    a2.x *= dt.z; a2.y *= dt.z; a2.z *= dt.z; a2.w *= dt.z;

    float4 vals[3] = { a0, a1, a2 };
    #pragma unroll
    for (int c = 0; c < 3; c++) {
        float4 v = vals[c];
        __nv_bfloat16 h0, h1, h2, h3, l0, l1, l2, l3;
        split_bf16(v.x, h0, l0); split_bf16(v.y, h1, l1);
        split_bf16(v.z, h2, l2); split_bf16(v.w, h3, l3);
        size_t off = ((size_t)(c + 1) * MAXN + gw) * D + fo;
        *(uint2*)(g_acth + off) = make_uint2(pack2(h0, h1), pack2(h2, h3));
        *(uint2*)(g_actl + off) = make_uint2(pack2(l0, l1), pack2(l2, l3));
    }
}

// ---------------- prepB: split weights to bf16 hi/lo, transposed [l][c][n][k] ----------------
__global__ void k_prepB(const float* __restrict__ Wself, const float* __restrict__ W3, int L) {
    int idx = blockIdx.x * blockDim.x + threadIdx.x;
    int total = L * 4 * D * D;
    if (idx >= total) return;
    int l  = idx / (4 * D * D);
    int r  = idx % (4 * D * D);
    int c  = r / (D * D);
    int nk = r % (D * D);
    int n  = nk >> 7;
    int k  = nk & 127;
    float v = (c == 0) ? Wself[l * D * D + k * D + n]
                       : W3[((l * 3) + (c - 1)) * D * D + k * D + n];
    __nv_bfloat16 hi, lo;
    split_bf16(v, hi, lo);
    g_Bhi[idx] = hi;
    g_Blo[idx] = lo;
}

// ---------------- warp-MMA GEMM (HMMA m16n8k16 bf16, fp32 acc) + fused LN epilogue ----------------
constexpr int APITCH = 72;
constexpr int OFF_A_HI = 0;
constexpr int OFF_A_LO = 128 * APITCH * 2;
constexpr int OFF_B_HI = 2 * 128 * APITCH * 2;
constexpr int OFF_B_LO = 3 * 128 * APITCH * 2;
constexpr int SMEM_GEMM = 4 * 128 * APITCH * 2;

__device__ __forceinline__ void mma16816(float* d, const uint32_t* a, const uint32_t* b) {
    asm volatile("mma.sync.aligned.m16n8k16.row.col.f32.bf16.bf16.f32 "
        "{%0,%1,%2,%3}, {%4,%5,%6,%7}, {%8,%9}, {%0,%1,%2,%3};"
        : "+f"(d[0]), "+f"(d[1]), "+f"(d[2]), "+f"(d[3])
        : "r"(a[0]), "r"(a[1]), "r"(a[2]), "r"(a[3]), "r"(b[0]), "r"(b[1]));
}

__global__ void __launch_bounds__(256, 2)
k_gemm_mma(int layer, const float* __restrict__ bias,
           const float* __restrict__ lng, const float* __restrict__ lnb,
           float* __restrict__ dout, int last, int N) {
    extern __shared__ char smem[];
    __nv_bfloat16* Ah = (__nv_bfloat16*)(smem + OFF_A_HI);
    __nv_bfloat16* Al = (__nv_bfloat16*)(smem + OFF_A_LO);
    __nv_bfloat16* Bh = (__nv_bfloat16*)(smem + OFF_B_HI);
    __nv_bfloat16* Bl = (__nv_bfloat16*)(smem + OFF_B_LO);

    int tid = threadIdx.x;
    int wid = tid >> 5;
    int lane = tid & 31;
    int group = lane >> 2;
    int tg = lane & 3;
    int warp_m = wid >> 2;
    int warp_n = wid & 3;
    int bm0 = blockIdx.x * 128;

    const __nv_bfloat16* BhiL = g_Bhi + (size_t)layer * 4 * D * D;
    const __nv_bfloat16* BloL = g_Blo + (size_t)layer * 4 * D * D;

    float acc[4][4][4];
    #pragma unroll
    for (int mt = 0; mt < 4; mt++)
        #pragma unroll
        for (int nt = 0; nt < 4; nt++)
            #pragma unroll
            for (int j = 0; j < 4; j++) acc[mt][nt][j] = 0.f;

    for (int chunk = 0; chunk < 8; chunk++) {
        int c = chunk >> 1;
        int koff = (chunk & 1) * 64;

        const __nv_bfloat16* ah = g_acth + ((size_t)c * MAXN + bm0) * D + koff;
        const __nv_bfloat16* al = g_actl + ((size_t)c * MAXN + bm0) * D + koff;
        #pragma unroll
        for (int i = 0; i < 4; i++) {
            int idx = tid + i * 256;
            int row = idx >> 3;
            int q = idx & 7;
            int so = row * APITCH + q * 8;
            size_t go = (size_t)row * D + q * 8;
            *(uint4*)(Ah + so) = *(const uint4*)(ah + go);
            *(uint4*)(Al + so) = *(const uint4*)(al + go);
        }
        const __nv_bfloat16* bh = BhiL + c * D * D + koff;
        const __nv_bfloat16* bl = BloL + c * D * D + koff;
        #pragma unroll
        for (int i = 0; i < 4; i++) {
            int idx = tid + i * 256;
            int row = idx >> 3;
            int q = idx & 7;
            int so = row * APITCH + q * 8;
            *(uint4*)(Bh + so) = *(const uint4*)(bh + row * D + q * 8);
            *(uint4*)(Bl + so) = *(const uint4*)(bl + row * D + q * 8);
        }
        __syncthreads();

        #pragma unroll
        for (int s = 0; s < 4; s++) {
            int ks = s * 16;
            uint32_t bhf[4][2], blf[4][2];
            #pragma unroll
            for (int nt = 0; nt < 4; nt++) {
                int n0 = warp_n * 32 + nt * 8 + group;
                int o = n0 * APITCH + ks + tg * 2;
                bhf[nt][0] = *(const uint32_t*)(Bh + o);
                bhf[nt][1] = *(const uint32_t*)(Bh + o + 8);
                blf[nt][0] = *(const uint32_t*)(Bl + o);
                blf[nt][1] = *(const uint32_t*)(Bl + o + 8);
            }
            #pragma unroll
            for (int mt = 0; mt < 4; mt++) {
                int r0 = warp_m * 64 + mt * 16 + group;
                int o = r0 * APITCH + ks + tg * 2;
                uint32_t ahf[4], alf[4];
                ahf[0] = *(const uint32_t*)(Ah + o);
                ahf[1] = *(const uint32_t*)(Ah + o + 8 * APITCH);
                ahf[2] = *(const uint32_t*)(Ah + o + 8);
                ahf[3] = *(const uint32_t*)(Ah + o + 8 * APITCH + 8);
                alf[0] = *(const uint32_t*)(Al + o);
                alf[1] = *(const uint32_t*)(Al + o + 8 * APITCH);
                alf[2] = *(const uint32_t*)(Al + o + 8);
                alf[3] = *(const uint32_t*)(Al + o + 8 * APITCH + 8);
                #pragma unroll
                for (int nt = 0; nt < 4; nt++) {
                    mma16816(acc[mt][nt], ahf, bhf[nt]);
                    mma16816(acc[mt][nt], ahf, blf[nt]);
                    mma16816(acc[mt][nt], alf, bhf[nt]);
                }
            }
        }
        __syncthreads();
    }

    // ---- add bias ----
    #pragma unroll
    for (int mt = 0; mt < 4; mt++)
        #pragma unroll
        for (int nt = 0; nt < 4; nt++) {
            int c0 = warp_n * 32 + nt * 8 + tg * 2;
            float b0 = bias[c0], b1 = bias[c0 + 1];
            acc[mt][nt][0] += b0; acc[mt][nt][1] += b1;
            acc[mt][nt][2] += b0; acc[mt][nt][3] += b1;
        }

    if (last) {
        #pragma unroll
        for (int mt = 0; mt < 4; mt++) {
            int r0 = bm0 + warp_m * 64 + mt * 16 + group;
            #pragma unroll
            for (int nt = 0; nt < 4; nt++) {
                int c0 = warp_n * 32 + nt * 8 + tg * 2;
                if (r0 < N)
                    *(float2*)(dout + (size_t)r0 * D + c0) = make_float2(acc[mt][nt][0], acc[mt][nt][1]);
                if (r0 + 8 < N)
                    *(float2*)(dout + (size_t)(r0 + 8) * D + c0) = make_float2(acc[mt][nt][2], acc[mt][nt][3]);
            }
        }
        return;
    }

    // ---- fused LayerNorm + ReLU + split-bf16 write (reuses staging smem) ----
    float* rsum = (float*)smem;            // [128][4]
    float* rsq  = rsum + 512;              // [128][4]

    #pragma unroll
    for (int mt = 0; mt < 4; mt++) {
        float slo = 0.f, shi = 0.f, qlo = 0.f, qhi = 0.f;
        #pragma unroll
        for (int nt = 0; nt < 4; nt++) {
            slo += acc[mt][nt][0] + acc[mt][nt][1];
            shi += acc[mt][nt][2] + acc[mt][nt][3];
            qlo += acc[mt][nt][0] * acc[mt][nt][0] + acc[mt][nt][1] * acc[mt][nt][1];
            qhi += acc[mt][nt][2] * acc[mt][nt][2] + acc[mt][nt][3] * acc[mt][nt][3];
        }
        #pragma unroll
        for (int o = 1; o < 4; o <<= 1) {
            slo += __shfl_xor_sync(0xffffffffu, slo, o);
            shi += __shfl_xor_sync(0xffffffffu, shi, o);
            qlo += __shfl_xor_sync(0xffffffffu, qlo, o);
            qhi += __shfl_xor_sync(0xffffffffu, qhi, o);
        }
        if (tg == 0) {
            int rl = warp_m * 64 + mt * 16 + group;
            rsum[rl * 4 + warp_n] = slo;
            rsq [rl * 4 + warp_n] = qlo;
            rsum[(rl + 8) * 4 + warp_n] = shi;
            rsq [(rl + 8) * 4 + warp_n] = qhi;
        }
    }
    __syncthreads();

    #pragma unroll
    for (int mt = 0; mt < 4; mt++) {
        int rl = warp_m * 64 + mt * 16 + group;       // local rows rl, rl+8
        float s0 = rsum[rl * 4 + 0] + rsum[rl * 4 + 1] + rsum[rl * 4 + 2] + rsum[rl * 4 + 3];
        float q0 = rsq [rl * 4 + 0] + rsq [rl * 4 + 1] + rsq [rl * 4 + 2] + rsq [rl * 4 + 3];
        float s1 = rsum[(rl + 8) * 4 + 0] + rsum[(rl + 8) * 4 + 1] + rsum[(rl + 8) * 4 + 2] + rsum[(rl + 8) * 4 + 3];
        float q1 = rsq [(rl + 8) * 4 + 0] + rsq [(rl + 8) * 4 + 1] + rsq [(rl + 8) * 4 + 2] + rsq [(rl + 8) * 4 + 3];
        float mu0 = s0 * (1.0f / 128.0f);
        float mu1 = s1 * (1.0f / 128.0f);
        float rs0 = rsqrtf(q0 * (1.0f / 128.0f) - mu0 * mu0 + 1e-5f);
        float rs1 = rsqrtf(q1 * (1.0f / 128.0f) - mu1 * mu1 + 1e-5f);
        int r0 = bm0 + rl;
        #pragma unroll
        for (int nt = 0; nt < 4; nt++) {
            int c0 = warp_n * 32 + nt * 8 + tg * 2;
            float gc0 = lng[c0], gc1 = lng[c0 + 1];
            float bc0 = lnb[c0], bc1 = lnb[c0 + 1];
            float y00 = fmaxf((acc[mt][nt][0] - mu0) * rs0 * gc0 + bc0, 0.f);
            float y01 = fmaxf((acc[mt][nt][1] - mu0) * rs0 * gc1 + bc1, 0.f);
            float y10 = fmaxf((acc[mt][nt][2] - mu1) * rs1 * gc0 + bc0, 0.f);
            float y11 = fmaxf((acc[mt][nt][3] - mu1) * rs1 * gc1 + bc1, 0.f);
            if (r0 < N) {
                *(float2*)(g_h + (size_t)r0 * D + c0) = make_float2(y00, y01);
                __nv_bfloat16 h0, h1, l0, l1;
                split_bf16(y00, h0, l0); split_bf16(y01, h1, l1);
                *(uint32_t*)(g_acth + (size_t)r0 * D + c0) = pack2(h0, h1);
                *(uint32_t*)(g_actl + (size_t)r0 * D + c0) = pack2(l0, l1);
            }
            if (r0 + 8 < N) {
                *(float2*)(g_h + (size_t)(r0 + 8) * D + c0) = make_float2(y10, y11);
                __nv_bfloat16 h0, h1, l0, l1;
                split_bf16(y10, h0, l0); split_bf16(y11, h1, l1);
                *(uint32_t*)(g_acth + (size_t)(r0 + 8) * D + c0) = pack2(h0, h1);
                *(uint32_t*)(g_actl + (size_t)(r0 + 8) * D + c0) = pack2(l0, l1);
            }
        }
    }
}

// ---------------- launch ----------------
extern "C" void kernel_launch(void* const* d_in, const int* in_sizes, int n_in,
                              void* d_out, int out_size) {
    const float* x    = (const float*)d_in[0];
    const int*   ei   = (const int*)d_in[1];
    const float* asp  = (const float*)d_in[2];
    const float* actx = (const float*)d_in[3];
    const float* alat = (const float*)d_in[4];
    const float* wsp  = (const float*)d_in[5];
    const float* wctx = (const float*)d_in[6];
    const float* wlat = (const float*)d_in[7];
    const float* W3   = (const float*)d_in[8];   // [L,3,D,D]
    const float* Wslf = (const float*)d_in[9];   // [L,D,D]
    const float* bias = (const float*)d_in[10];  // [L,D]
    const float* degp = (const float*)d_in[11];  // [L,3]
    const float* lng  = (const float*)d_in[12];
    const float* lnb  = (const float*)d_in[13];
    float* out = (float*)d_out;

    int N = in_sizes[0] / D;
    int E = in_sizes[2];
    int L = in_sizes[10] / D;
    int nblk = (N + 255) / 256;

    cudaFuncSetAttribute(k_gemm_mma, cudaFuncAttributeMaxDynamicSharedMemorySize, SMEM_GEMM);

    k_init<<<(N + 255) / 256, 256>>>(N);
    k_edge1<<<(E + 255) / 256, 256>>>(ei, N, E);
    k_scan1<<<nblk, 256>>>(N);
    k_scan2<<<1, 256>>>(nblk, E, N);
    k_scan3<<<nblk, 256>>>(N);
    k_edge2<<<(E + 255) / 256, 256>>>(ei, asp, actx, alat, wsp, wctx, wlat, N, E);
    k_deg<<<(N * 32 + 255) / 256, 256>>>(N);
    k_dinv4<<<(L * N + 255) / 256, 256>>>(degp, L, N);
    k_prepB<<<(L * 4 * D * D + 255) / 256, 256>>>(Wslf, W3, L);
    k_prepX<<<(N * (D / 4) + 255) / 256, 256>>>(x, N);

    int gemm_grid = (N + 127) / 128;
    for (int l = 0; l < L; l++) {
        int use_h = (l > 0) ? 1 : 0;
        int last = (l == L - 1) ? 1 : 0;
        k_agg<<<(N * 32 + 255) / 256, 256>>>(x, use_h, l, N);
        k_gemm_mma<<<gemm_grid, 256, SMEM_GEMM>>>(l, bias + l * D, lng, lnb, out, last, N);
    }
}